// round 7
// baseline (speedup 1.0000x reference)
#include <cuda_runtime.h>
#include <math.h>
#include <stdint.h>

// Problem constants
#define CB 16
#define CS 512
#define CH 768
#define CT 2
#define CN 32
#define CL 64
#define CE 8
#define CD 128
#define CA 128

// ---------------- scratch (device globals; no allocation allowed) ----------------
__device__ float g_kbuf[CB*CT*CN*CL*CD];       // neighbor k projections
__device__ float g_msgs[CB*CT*CN*CE*CH];       // per-neighbor messages
__device__ float g_score[CB*CT*CN];
__device__ float g_c1[CB*CT];
__device__ float g_qe[CB*CT*CE*CD];
__device__ float g_efea[CB*CT*CE*CH];          // gathered entity span features [256,768]
__device__ float g_x[CB*CS*CH];
__device__ float g_qk2[CB*CS*2*CD];            // fused q2|k2 [B*S, 256]
__device__ float g_v2T[CB*CH*CS];              // v2 transposed per batch [B][768][512]
__device__ float g_s2[CB*CS*CS];
__device__ float g_wqkT[2*CD*CH];              // [WqT; WkT] [256,768]
__device__ float g_wvT[CH*CH];
__device__ float g_bqk[2*CD];

// ======== tf32 mma.sync GEMM: C = alpha * A @ B^T (+bias), CTA 256x128, warp 64x64 ========
// A [M,K] rows lda, B [N,K] rows ldb, C [M,N] rows ldc. M mult 256, N mult 128, K mult 32.
// bias_mode: 0 none, 1 per-col, 2 per-row. Batched via blockIdx.z (strides sA,sB,sC).
// 256 threads = 8 warps (warpM 0..3 x warpN 0..1). SMEM in m16n8k8 fragment order:
//   A: [4 ks][16 mt][32 lane][4 jfrag]   B: [4 ks][16 nt][32 lane][2 jfrag]

#define GE_SMEM_BYTES 98304   // 2 * (A 32KB + B 16KB)

__device__ __forceinline__ void mma_tf32(float c[4], const uint32_t a[4], const uint32_t b[2]) {
    asm volatile(
        "mma.sync.aligned.m16n8k8.row.col.f32.tf32.tf32.f32 "
        "{%0,%1,%2,%3}, {%4,%5,%6,%7}, {%8,%9}, {%0,%1,%2,%3};"
        : "+f"(c[0]), "+f"(c[1]), "+f"(c[2]), "+f"(c[3])
        : "r"(a[0]), "r"(a[1]), "r"(a[2]), "r"(a[3]), "r"(b[0]), "r"(b[1]));
}

__device__ __forceinline__ float4 ld_tf32_4(const float* __restrict__ p) {
    float4 v = *reinterpret_cast<const float4*>(p);
    asm volatile("cvt.rna.tf32.f32 %0, %0;" : "+r"(*(uint32_t*)&v.x));
    asm volatile("cvt.rna.tf32.f32 %0, %0;" : "+r"(*(uint32_t*)&v.y));
    asm volatile("cvt.rna.tf32.f32 %0, %0;" : "+r"(*(uint32_t*)&v.z));
    asm volatile("cvt.rna.tf32.f32 %0, %0;" : "+r"(*(uint32_t*)&v.w));
    return v;
}

// A tile: 256 rows x 32 cols, 8 float4 per thread
__device__ __forceinline__ void ldgA(const float* __restrict__ p, int lda, int tid, float4 r[8]) {
    #pragma unroll
    for (int j = 0; j < 8; j++) {
        int f = j * 256 + tid;
        r[j] = ld_tf32_4(p + (long long)(f >> 3) * lda + (f & 7) * 4);
    }
}
// B tile: 128 rows x 32 cols, 4 float4 per thread
__device__ __forceinline__ void ldgB(const float* __restrict__ p, int ldb, int tid, float4 r[4]) {
    #pragma unroll
    for (int j = 0; j < 4; j++) {
        int f = j * 256 + tid;
        r[j] = ld_tf32_4(p + (long long)(f >> 3) * ldb + (f & 7) * 4);
    }
}

__device__ __forceinline__ void sts_fragA(float* sm, int tid, const float4 r[8]) {
    #pragma unroll
    for (int j = 0; j < 8; j++) {
        int f = j * 256 + tid;
        int row = f >> 3, c4 = f & 7;
        int ks = c4 >> 1;
        int jf = ((row >> 3) & 1) | ((c4 & 1) << 1);
        int mt = row >> 4, g = row & 7;
        float* base = sm + (((ks * 16 + mt) * 32 + g * 4) << 2) + jf;
        const float* v = reinterpret_cast<const float*>(&r[j]);
        #pragma unroll
        for (int t = 0; t < 4; t++) base[t << 2] = v[t];
    }
}

__device__ __forceinline__ void sts_fragB(float* sm, int tid, const float4 r[4]) {
    #pragma unroll
    for (int j = 0; j < 4; j++) {
        int f = j * 256 + tid;
        int row = f >> 3, c4 = f & 7;
        int ks = c4 >> 1;
        int jf = c4 & 1;
        int nt = row >> 3, g = row & 7;
        float* base = sm + (((ks * 16 + nt) * 32 + g * 4) << 1) + jf;
        const float* v = reinterpret_cast<const float*>(&r[j]);
        #pragma unroll
        for (int t = 0; t < 4; t++) base[t << 1] = v[t];
    }
}

__global__ void __launch_bounds__(256)
mm_gemm_kernel(const float* __restrict__ A, const float* __restrict__ B,
               const float* __restrict__ bias, float* __restrict__ C,
               int M, int N, int K, float alpha,
               int lda, int ldb, int ldc, int bias_mode,
               long long sA, long long sB, long long sC)
{
    extern __shared__ float smem[];
    float* smA[2] = { smem,          smem + 12288 };   // 8192 A + 4096 B per buffer
    float* smB[2] = { smem + 8192,   smem + 20480 };

    int tid = threadIdx.x;
    int wid = tid >> 5, lane = tid & 31;
    int warpM = wid & 3;           // 0..3 -> 64-row slab
    int warpN = wid >> 2;          // 0..1 -> 64-col slab

    const float* Ab = A + (long long)blockIdx.z * sA + (long long)(blockIdx.y * 256) * lda;
    const float* Bb = B + (long long)blockIdx.z * sB + (long long)(blockIdx.x * 128) * ldb;

    float acc[4][8][4];
    #pragma unroll
    for (int i = 0; i < 4; i++)
        #pragma unroll
        for (int j = 0; j < 8; j++)
            #pragma unroll
            for (int c = 0; c < 4; c++) acc[i][j][c] = 0.f;

    int nch = K >> 5;
    float4 ra[8], rb[4];
    ldgA(Ab, lda, tid, ra);
    ldgB(Bb, ldb, tid, rb);
    sts_fragA(smA[0], tid, ra);
    sts_fragB(smB[0], tid, rb);
    __syncthreads();

    for (int i = 0; i < nch; i++) {
        int buf = i & 1;
        if (i + 1 < nch) {
            ldgA(Ab + (i + 1) * 32, lda, tid, ra);
            ldgB(Bb + (i + 1) * 32, ldb, tid, rb);
        }
        const float* fA = smA[buf] + ((warpM * 4) * 32 + lane) * 4;
        const float* fB = smB[buf] + ((warpN * 8) * 32 + lane) * 2;
        #pragma unroll
        for (int ks = 0; ks < 4; ks++) {
            uint32_t afr[4][4];
            #pragma unroll
            for (int mt = 0; mt < 4; mt++) {
                float4 v = *reinterpret_cast<const float4*>(fA + (ks * 16 + mt) * 128);
                afr[mt][0] = __float_as_uint(v.x); afr[mt][1] = __float_as_uint(v.y);
                afr[mt][2] = __float_as_uint(v.z); afr[mt][3] = __float_as_uint(v.w);
            }
            #pragma unroll
            for (int nt = 0; nt < 8; nt++) {
                float2 v = *reinterpret_cast<const float2*>(fB + (ks * 16 + nt) * 64);
                uint32_t bfr[2] = { __float_as_uint(v.x), __float_as_uint(v.y) };
                #pragma unroll
                for (int mt = 0; mt < 4; mt++) mma_tf32(acc[mt][nt], afr[mt], bfr);
            }
        }
        __syncthreads();
        if (i + 1 < nch) {
            sts_fragA(smA[buf ^ 1], tid, ra);
            sts_fragB(smB[buf ^ 1], tid, rb);
            __syncthreads();
        }
    }

    int g = lane >> 2, t = lane & 3;
    float* Cb = C + (long long)blockIdx.z * sC;
    #pragma unroll
    for (int mt = 0; mt < 4; mt++) {
        long long r0 = (long long)(blockIdx.y * 256 + warpM * 64 + mt * 16 + g);
        float br0 = 0.f, br1 = 0.f;
        if (bias_mode == 2) { br0 = bias[r0]; br1 = bias[r0 + 8]; }
        #pragma unroll
        for (int nt = 0; nt < 8; nt++) {
            int cc = blockIdx.x * 128 + warpN * 64 + nt * 8 + t * 2;
            float bcx = 0.f, bcy = 0.f;
            if (bias_mode == 1) { bcx = bias[cc]; bcy = bias[cc + 1]; }
            float2 v0 = { acc[mt][nt][0] * alpha + bcx + br0, acc[mt][nt][1] * alpha + bcy + br0 };
            float2 v1 = { acc[mt][nt][2] * alpha + bcx + br1, acc[mt][nt][3] * alpha + bcy + br1 };
            *reinterpret_cast<float2*>(Cb + r0 * ldc + cc) = v0;
            *reinterpret_cast<float2*>(Cb + (r0 + 8) * ldc + cc) = v1;
        }
    }
}

// ---------------- transpose: dst[C,R] = src[R,C]^T ----------------
__global__ void transpose_kernel(const float* __restrict__ src, float* __restrict__ dst,
                                 int R, int C) {
    __shared__ float t[32][33];
    int r0 = blockIdx.y * 32, c0 = blockIdx.x * 32;
    int x = threadIdx.x, y = threadIdx.y;     // 32 x 8
    #pragma unroll
    for (int j = 0; j < 32; j += 8)
        if (r0 + y + j < R && c0 + x < C)
            t[y + j][x] = src[(long long)(r0 + y + j) * C + c0 + x];
    __syncthreads();
    #pragma unroll
    for (int j = 0; j < 32; j += 8)
        if (c0 + y + j < C && r0 + x < R)
            dst[(long long)(c0 + y + j) * R + r0 + x] = t[x][y + j];
}

// ---------------- pack [bq;bk] ----------------
__global__ void pack_bqk_kernel(const float* __restrict__ bq, const float* __restrict__ bk) {
    int i = threadIdx.x;
    g_bqk[i] = (i < CD) ? bq[i] : bk[i - CD];
}

// ---------------- gather entity span features: g_efea[bt*E+e][h] ----------------
__global__ void gather_efea_kernel(const float* __restrict__ xs, const int* __restrict__ spans) {
    int i4 = blockIdx.x * blockDim.x + threadIdx.x;        // over 256*768/4
    if (i4 >= CB * CT * CE * CH / 4) return;
    int f = i4 * 4;
    int row = f / CH, c = f % CH;
    int bt = row >> 3, e = row & 7;
    int b = bt >> 1;
    int span = spans[bt];
    *reinterpret_cast<float4*>(&g_efea[f]) =
        *reinterpret_cast<const float4*>(&xs[((long long)b * CS + span + e) * CH + c]);
}

// ---------------- feas = mean_e efea; wf = feas@Ww+bw; c1 = wf . Wa[0:A] ----------------
__global__ void feasC1_kernel(const float* __restrict__ Ww, const float* __restrict__ bw,
                              const float* __restrict__ Wa) {
    int bt = blockIdx.x;           // 32 blocks, 128 threads
    int tid = threadIdx.x;
    __shared__ float s_f[CH];
    __shared__ float s_r[4];
    for (int h = tid; h < CH; h += 128) {
        float a = 0.f;
        #pragma unroll
        for (int e = 0; e < CE; e++) a += g_efea[(bt * CE + e) * CH + h];
        s_f[h] = a * (1.0f / CE);
    }
    __syncthreads();
    float acc = bw[tid];
    for (int h = 0; h < CH; h++) acc += s_f[h] * Ww[h * CA + tid];
    float part = acc * Wa[tid];
    #pragma unroll
    for (int off = 16; off; off >>= 1) part += __shfl_xor_sync(0xffffffffu, part, off);
    if ((tid & 31) == 0) s_r[tid >> 5] = part;
    __syncthreads();
    if (tid == 0) g_c1[bt] = s_r[0] + s_r[1] + s_r[2] + s_r[3];
}

// ---------------- stage B: per-neighbor SDPA + messages + score ----------------
__global__ void stageB_kernel(const float* __restrict__ neigh, const float* __restrict__ dists,
                              const float* __restrict__ Ww, const float* __restrict__ bw,
                              const float* __restrict__ Wa, const float* __restrict__ ba,
                              const float* __restrict__ wb, const float* __restrict__ bb) {
    int bid = blockIdx.x;
    int bt = bid / CN, n = bid % CN;
    int tid = threadIdx.x;
    const float inv_sqrt_d = 0.08838834764831845f;

    __shared__ float s_q[CE][CD];
    __shared__ float s_kc[CL][CD + 1];
    __shared__ float s_attn[CE][CL];
    __shared__ float s_pooled[CH];
    __shared__ float s_red[256];

    for (int i = tid; i < CE * CD; i += 256) s_q[i / CD][i % CD] = g_qe[bt * CE * CD + i];
    const long long kb = ((long long)bid) * CL * CD;
    for (int i = tid; i < CL * CD; i += 256) {
        int l = i >> 7, d = i & 127;
        s_kc[l][d] = g_kbuf[kb + i];
    }
    __syncthreads();

    for (int o = tid; o < CE * CL; o += 256) {
        int e = o / CL, l = o % CL;
        float acc = 0.f;
        #pragma unroll 8
        for (int d = 0; d < CD; d++) acc += s_q[e][d] * s_kc[l][d];
        s_attn[e][l] = acc * inv_sqrt_d;
    }
    __syncthreads();

    {
        int w = tid >> 5, lane = tid & 31;
        if (w < CE) {
            float v1 = s_attn[w][lane], v2 = s_attn[w][lane + 32];
            float m = fmaxf(v1, v2);
            #pragma unroll
            for (int off = 16; off; off >>= 1) m = fmaxf(m, __shfl_xor_sync(0xffffffffu, m, off));
            float e1 = __expf(v1 - m), e2 = __expf(v2 - m);
            float s = e1 + e2;
            #pragma unroll
            for (int off = 16; off; off >>= 1) s += __shfl_xor_sync(0xffffffffu, s, off);
            float inv = 1.0f / s;
            s_attn[w][lane] = e1 * inv;
            s_attn[w][lane + 32] = e2 * inv;
        }
    }
    __syncthreads();

    const long long nb = ((long long)bid) * CL * CH;
    const long long mb = ((long long)bid) * CE * CH;
    for (int hc = 0; hc < CH; hc += 128) {
        for (int i = tid; i < CL * 128; i += 256) {
            int l = i >> 7, j = i & 127;
            s_kc[l][j] = neigh[nb + (long long)l * CH + hc + j];
        }
        __syncthreads();
        float local = 0.f;
        #pragma unroll
        for (int rep = 0; rep < 4; rep++) {
            int o = tid + rep * 256;
            int e = o >> 7, j = o & 127;
            float acc = 0.f;
            #pragma unroll 8
            for (int l = 0; l < CL; l++) acc += s_attn[e][l] * s_kc[l][j];
            g_msgs[mb + (long long)e * CH + hc + j] = acc;
            local += acc;
        }
        s_red[tid] = local;
        __syncthreads();
        if (tid < 128) s_pooled[hc + tid] = (s_red[tid] + s_red[tid + 128]) * (1.0f / CE);
        __syncthreads();
    }

    float part = 0.f;
    if (tid < CA) {
        float acc = bw[tid];
        for (int h = 0; h < CH; h++) acc += s_pooled[h] * Ww[h * CA + tid];
        part = acc * Wa[CA + tid];
    }
    s_red[tid] = part;
    __syncthreads();
    for (int s = 128; s > 0; s >>= 1) {
        if (tid < s) s_red[tid] += s_red[tid + s];
        __syncthreads();
    }
    if (tid == 0) {
        float v = g_c1[bt] + s_red[0] + ba[0];
        v = (v > 0.f) ? v : 0.01f * v;
        v += dists[bt * CN + n] * wb[0] + bb[0];
        g_score[bt * CN + n] = 1.0f / (1.0f + __expf(-v));
    }
}

// ---------------- copy xs -> x ----------------
__global__ void copy_kernel(const float* __restrict__ xs) {
    long long i = (long long)blockIdx.x * blockDim.x + threadIdx.x;
    const long long n4 = (long long)CB * CS * CH / 4;
    if (i < n4) reinterpret_cast<float4*>(g_x)[i] = reinterpret_cast<const float4*>(xs)[i];
}

// ---------------- scatter delta into spans (one t per launch) ----------------
__global__ void scatter_kernel(const int* __restrict__ spans, int t) {
    int i = blockIdx.x * blockDim.x + threadIdx.x;
    if (i >= CB * CE * CH) return;
    int b = i / (CE * CH);
    int r = i % (CE * CH);
    int e = r / CH, h = r % CH;
    int bt = b * CT + t;
    float val = 0.f;
    const float* sc = &g_score[bt * CN];
    const float* ms = &g_msgs[(((long long)bt * CN) * CE + e) * CH + h];
    #pragma unroll 8
    for (int n = 0; n < CN; n++) val += sc[n] * ms[(long long)n * CE * CH];
    int span = spans[bt];
    g_x[((long long)b * CS + span + e) * CH + h] += val;
}

// ---------------- row softmax for s2 ----------------
__global__ void softmax_kernel() {
    int row = blockIdx.x;
    int tid = threadIdx.x;
    float* p = &g_s2[(long long)row * CS];
    __shared__ float s_red[256];
    float v1 = p[tid], v2 = p[tid + 256];
    float m = fmaxf(v1, v2);
    s_red[tid] = m;
    __syncthreads();
    for (int s = 128; s > 0; s >>= 1) { if (tid < s) s_red[tid] = fmaxf(s_red[tid], s_red[tid + s]); __syncthreads(); }
    m = s_red[0];
    __syncthreads();
    float e1 = __expf(v1 - m), e2 = __expf(v2 - m);
    s_red[tid] = e1 + e2;
    __syncthreads();
    for (int s = 128; s > 0; s >>= 1) { if (tid < s) s_red[tid] += s_red[tid + s]; __syncthreads(); }
    float inv = 1.0f / s_red[0];
    p[tid] = e1 * inv;
    p[tid + 256] = e2 * inv;
}

// ---------------- host ----------------
extern "C" void kernel_launch(void* const* d_in, const int* in_sizes, int n_in,
                              void* d_out, int out_size) {
    const float* xs    = (const float*)d_in[0];
    const float* neigh = (const float*)d_in[1];
    const float* dists = (const float*)d_in[2];
    const int*   spans = (const int*)d_in[3];
    const float* Wq = (const float*)d_in[4];
    const float* bq = (const float*)d_in[5];
    const float* Wk = (const float*)d_in[6];
    const float* bk = (const float*)d_in[7];
    const float* Wv = (const float*)d_in[8];
    const float* bv = (const float*)d_in[9];
    const float* Ww = (const float*)d_in[10];
    const float* bw = (const float*)d_in[11];
    const float* Wa = (const float*)d_in[12];
    const float* ba = (const float*)d_in[13];
    const float* wb = (const float*)d_in[14];
    const float* bb = (const float*)d_in[15];
    float* out = (float*)d_out;

    float *kbuf, *x, *qk2, *v2T, *s2, *wqkT, *wvT, *bqk, *efea, *qe;
    cudaGetSymbolAddress((void**)&kbuf, g_kbuf);
    cudaGetSymbolAddress((void**)&x,    g_x);
    cudaGetSymbolAddress((void**)&qk2,  g_qk2);
    cudaGetSymbolAddress((void**)&v2T,  g_v2T);
    cudaGetSymbolAddress((void**)&s2,   g_s2);
    cudaGetSymbolAddress((void**)&wqkT, g_wqkT);
    cudaGetSymbolAddress((void**)&wvT,  g_wvT);
    cudaGetSymbolAddress((void**)&bqk,  g_bqk);
    cudaGetSymbolAddress((void**)&efea, g_efea);
    cudaGetSymbolAddress((void**)&qe,   g_qe);

    cudaFuncSetAttribute(mm_gemm_kernel, cudaFuncAttributeMaxDynamicSharedMemorySize, GE_SMEM_BYTES);

    const float inv_sqrt_d = 0.08838834764831845f;
    dim3 tb(32, 8);

    // weight prep: wqkT = [WqT; WkT], wvT = Wv^T, bqk = [bq; bk]
    transpose_kernel<<<dim3(4, 24), tb>>>(Wq, wqkT, CH, CD);
    transpose_kernel<<<dim3(4, 24), tb>>>(Wk, wqkT + CD * CH, CH, CD);
    transpose_kernel<<<dim3(24, 24), tb>>>(Wv, wvT, CH, CH);
    pack_bqk_kernel<<<1, 2 * CD>>>(bq, bk);

    // entity features -> q (via tensor GEMM), feas/c1
    gather_efea_kernel<<<(CB*CT*CE*CH/4 + 255) / 256, 256>>>(xs, spans);
    mm_gemm_kernel<<<dim3(1, 1, 1), 256, GE_SMEM_BYTES>>>(
        efea, wqkT, bq, qe, CB*CT*CE, CD, CH, 1.0f, CH, CH, CD, 1, 0, 0, 0);
    feasC1_kernel<<<CB * CT, 128>>>(Ww, bw, Wa);

    // k projection: [65536,768] @ WkT^T -> [65536,128]
    mm_gemm_kernel<<<dim3(1, 256, 1), 256, GE_SMEM_BYTES>>>(
        neigh, wqkT + CD * CH, bk, kbuf, CB*CT*CN*CL, CD, CH, 1.0f, CH, CH, CD, 1, 0, 0, 0);

    // per-neighbor SDPA + messages + scores
    stageB_kernel<<<CB * CT * CN, 256>>>(neigh, dists, Ww, bw, Wa, ba, wb, bb);

    // x = xs; scatter deltas (t=0, t=1 sequential: deterministic)
    copy_kernel<<<(CB * CS * CH / 4 + 255) / 256, 256>>>(xs);
    scatter_kernel<<<(CB * CE * CH + 255) / 256, 256>>>(spans, 0);
    scatter_kernel<<<(CB * CE * CH + 255) / 256, 256>>>(spans, 1);

    // fused q2|k2 projection: [8192,768] @ wqkT^T -> [8192,256]
    mm_gemm_kernel<<<dim3(2, 32, 1), 256, GE_SMEM_BYTES>>>(
        x, wqkT, bqk, qk2, CB * CS, 2 * CD, CH, 1.0f, CH, CH, 2 * CD, 1, 0, 0, 0);

    // v2T = wvT @ x^T per batch: [768,512], row-bias bv
    mm_gemm_kernel<<<dim3(4, 3, CB), 256, GE_SMEM_BYTES>>>(
        wvT, x, bv, v2T, CH, CS, CH, 1.0f, CH, CH, CS, 2,
        0, (long long)CS * CH, (long long)CH * CS);

    // s2 = q2 @ k2^T * inv_sqrt_d (batched; q2/k2 interleaved in qk2)
    mm_gemm_kernel<<<dim3(4, 2, CB), 256, GE_SMEM_BYTES>>>(
        qk2, qk2 + CD, nullptr, s2, CS, CS, CD, inv_sqrt_d, 2 * CD, 2 * CD, CS, 0,
        (long long)CS * 2 * CD, (long long)CS * 2 * CD, (long long)CS * CS);

    softmax_kernel<<<CB * CS, 256>>>();

    // out = softmax(s2) @ v2  (B operand = v2T [768,512], batched)
    mm_gemm_kernel<<<dim3(6, 2, CB), 256, GE_SMEM_BYTES>>>(
        s2, v2T, nullptr, out, CS, CH, CS, 1.0f, CS, CS, CH, 0,
        (long long)CS * CS, (long long)CH * CS, (long long)CS * CH);
}

// round 9
// speedup vs baseline: 1.1535x; 1.1535x over previous
#include <cuda_runtime.h>
#include <math.h>
#include <stdint.h>

// Problem constants
#define CB 16
#define CS 512
#define CH 768
#define CT 2
#define CN 32
#define CL 64
#define CE 8
#define CD 128
#define CA 128

// ---------------- scratch (device globals; no allocation allowed) ----------------
__device__ float g_kbuf[CB*CT*CN*CL*CD];       // neighbor k projections
__device__ float g_msgs[CB*CT*CN*CE*CH];       // per-neighbor messages
__device__ float g_score[CB*CT*CN];
__device__ float g_c1[CB*CT];
__device__ float g_qe[CB*CT*CE*CD];
__device__ float g_efea[CB*CT*CE*CH];          // gathered entity span features [256,768]
__device__ float g_x[CB*CS*CH];
__device__ float g_qk2[CB*CS*2*CD];            // fused q2|k2 [B*S, 256]
__device__ float g_v2T[CB*CH*CS];              // v2 transposed per batch [B][768][512]
__device__ float g_s2[CB*CS*CS];
__device__ float g_wqkT[2*CD*CH];              // [WqT; WkT] [256,768]
__device__ float g_wvT[CH*CH];
__device__ float g_bqk[2*CD];

// ================= tf32 mma.sync GEMM (R6 config: CTA 128x128, warp 32x64) =================
// A [M,K] rows lda, B [N,K] rows ldb, C [M,N] rows ldc. M,N mult 128, K mult 32.
// bias_mode: 0 none, 1 per-col, 2 per-row. Batched via blockIdx.z (strides sA,sB,sC).

#define GE_SMEM_BYTES 65536

__device__ __forceinline__ void mma_tf32(float c[4], const uint32_t a[4], const uint32_t b[2]) {
    asm volatile(
        "mma.sync.aligned.m16n8k8.row.col.f32.tf32.tf32.f32 "
        "{%0,%1,%2,%3}, {%4,%5,%6,%7}, {%8,%9}, {%0,%1,%2,%3};"
        : "+f"(c[0]), "+f"(c[1]), "+f"(c[2]), "+f"(c[3])
        : "r"(a[0]), "r"(a[1]), "r"(a[2]), "r"(a[3]), "r"(b[0]), "r"(b[1]));
}

__device__ __forceinline__ void tile_ldg(const float* __restrict__ p, int lda, int tid, float4 r[4]) {
    #pragma unroll
    for (int j = 0; j < 4; j++) {
        int f = j * 256 + tid;
        int row = f >> 3, c4 = f & 7;
        float4 v = *reinterpret_cast<const float4*>(p + (long long)row * lda + c4 * 4);
        asm volatile("cvt.rna.tf32.f32 %0, %0;" : "+r"(*(uint32_t*)&v.x));
        asm volatile("cvt.rna.tf32.f32 %0, %0;" : "+r"(*(uint32_t*)&v.y));
        asm volatile("cvt.rna.tf32.f32 %0, %0;" : "+r"(*(uint32_t*)&v.z));
        asm volatile("cvt.rna.tf32.f32 %0, %0;" : "+r"(*(uint32_t*)&v.w));
        r[j] = v;
    }
}

__device__ __forceinline__ void sts_fragA(float* sm, int tid, const float4 r[4]) {
    #pragma unroll
    for (int j = 0; j < 4; j++) {
        int f = j * 256 + tid;
        int row = f >> 3, c4 = f & 7;
        int ks = c4 >> 1;
        int jfrag = ((row >> 3) & 1) + ((c4 & 1) << 1);
        int mt = row >> 4, g = row & 7;
        float* base = sm + (((ks * 8 + mt) * 32 + g * 4) << 2) + jfrag;
        const float* v = reinterpret_cast<const float*>(&r[j]);
        #pragma unroll
        for (int t = 0; t < 4; t++) base[t << 2] = v[t];
    }
}

__device__ __forceinline__ void sts_fragB(float* sm, int tid, const float4 r[4]) {
    #pragma unroll
    for (int j = 0; j < 4; j++) {
        int f = j * 256 + tid;
        int row = f >> 3, c4 = f & 7;
        int ks = c4 >> 1;
        int jfrag = c4 & 1;
        int nt = row >> 3, g = row & 7;
        float* base = sm + (((ks * 16 + nt) * 32 + g * 4) << 1) + jfrag;
        const float* v = reinterpret_cast<const float*>(&r[j]);
        #pragma unroll
        for (int t = 0; t < 4; t++) base[t << 1] = v[t];
    }
}

__global__ void __launch_bounds__(256)
mm_gemm_kernel(const float* __restrict__ A, const float* __restrict__ B,
               const float* __restrict__ bias, float* __restrict__ C,
               int M, int N, int K, float alpha,
               int lda, int ldb, int ldc, int bias_mode,
               long long sA, long long sB, long long sC)
{
    extern __shared__ float smem[];
    float* smA[2] = { smem,          smem + 8192 };
    float* smB[2] = { smem + 4096,   smem + 12288 };

    int tid = threadIdx.x;
    int wid = tid >> 5, lane = tid & 31;
    int warpM = wid & 3;
    int warpN = wid >> 2;

    const float* Ab = A + (long long)blockIdx.z * sA + (long long)(blockIdx.y * 128) * lda;
    const float* Bb = B + (long long)blockIdx.z * sB + (long long)(blockIdx.x * 128) * ldb;

    float acc[2][8][4];
    #pragma unroll
    for (int i = 0; i < 2; i++)
        #pragma unroll
        for (int j = 0; j < 8; j++)
            #pragma unroll
            for (int c = 0; c < 4; c++) acc[i][j][c] = 0.f;

    int nch = K >> 5;
    float4 ra[4], rb[4];
    tile_ldg(Ab, lda, tid, ra);
    tile_ldg(Bb, ldb, tid, rb);
    sts_fragA(smA[0], tid, ra);
    sts_fragB(smB[0], tid, rb);
    __syncthreads();

    for (int i = 0; i < nch; i++) {
        int buf = i & 1;
        if (i + 1 < nch) {
            tile_ldg(Ab + (i + 1) * 32, lda, tid, ra);
            tile_ldg(Bb + (i + 1) * 32, ldb, tid, rb);
        }
        const float* fA = smA[buf] + ((warpM * 2) * 32 + lane) * 4;
        const float* fB = smB[buf] + ((warpN * 8) * 32 + lane) * 2;
        #pragma unroll
        for (int ks = 0; ks < 4; ks++) {
            uint32_t afr[2][4];
            #pragma unroll
            for (int mt = 0; mt < 2; mt++) {
                float4 v = *reinterpret_cast<const float4*>(fA + (ks * 8 + mt) * 128);
                afr[mt][0] = __float_as_uint(v.x); afr[mt][1] = __float_as_uint(v.y);
                afr[mt][2] = __float_as_uint(v.z); afr[mt][3] = __float_as_uint(v.w);
            }
            #pragma unroll
            for (int nt = 0; nt < 8; nt++) {
                float2 v = *reinterpret_cast<const float2*>(fB + (ks * 16 + nt) * 64);
                uint32_t bfr[2] = { __float_as_uint(v.x), __float_as_uint(v.y) };
                mma_tf32(acc[0][nt], afr[0], bfr);
                mma_tf32(acc[1][nt], afr[1], bfr);
            }
        }
        __syncthreads();
        if (i + 1 < nch) {
            sts_fragA(smA[buf ^ 1], tid, ra);
            sts_fragB(smB[buf ^ 1], tid, rb);
            __syncthreads();
        }
    }

    int g = lane >> 2, t = lane & 3;
    long long crow0 = (long long)(blockIdx.y * 128 + warpM * 32 + g);
    int col0 = blockIdx.x * 128 + warpN * 64 + t * 2;
    float* Cb = C + (long long)blockIdx.z * sC;
    #pragma unroll
    for (int mt = 0; mt < 2; mt++) {
        long long r0 = crow0 + mt * 16;
        float br0 = 0.f, br1 = 0.f;
        if (bias_mode == 2) { br0 = bias[r0]; br1 = bias[r0 + 8]; }
        #pragma unroll
        for (int nt = 0; nt < 8; nt++) {
            int cc = col0 + nt * 8;
            float bcx = 0.f, bcy = 0.f;
            if (bias_mode == 1) { bcx = bias[cc]; bcy = bias[cc + 1]; }
            float2 v0 = { acc[mt][nt][0] * alpha + bcx + br0, acc[mt][nt][1] * alpha + bcy + br0 };
            float2 v1 = { acc[mt][nt][2] * alpha + bcx + br1, acc[mt][nt][3] * alpha + bcy + br1 };
            *reinterpret_cast<float2*>(Cb + r0 * ldc + cc) = v0;
            *reinterpret_cast<float2*>(Cb + (r0 + 8) * ldc + cc) = v1;
        }
    }
}

// ---------------- prep: all weight transposes + bias pack in ONE launch ----------------
// blocks 0..95: Wq^T tiles; 96..191: Wk^T; 192..767: Wv^T; 768: pack bqk.
__global__ void prep_kernel(const float* __restrict__ Wq, const float* __restrict__ Wk,
                            const float* __restrict__ Wv,
                            const float* __restrict__ bq, const float* __restrict__ bk) {
    int bid = blockIdx.x;
    int x = threadIdx.x, y = threadIdx.y;      // 32 x 8
    if (bid == 768) {
        int i = y * 32 + x;
        g_bqk[i] = (i < CD) ? bq[i] : bk[i - CD];
        return;
    }
    const float* src; float* dst; int R, C, tile;
    if (bid < 96)       { src = Wq; dst = g_wqkT;            R = CH; C = CD; tile = bid; }
    else if (bid < 192) { src = Wk; dst = g_wqkT + CD * CH;  R = CH; C = CD; tile = bid - 96; }
    else                { src = Wv; dst = g_wvT;             R = CH; C = CH; tile = bid - 192; }
    int tcols = C >> 5;
    int c0 = (tile % tcols) * 32, r0 = (tile / tcols) * 32;
    __shared__ float t[32][33];
    #pragma unroll
    for (int j = 0; j < 32; j += 8)
        t[y + j][x] = src[(long long)(r0 + y + j) * C + c0 + x];
    __syncthreads();
    #pragma unroll
    for (int j = 0; j < 32; j += 8)
        dst[(long long)(c0 + y + j) * R + r0 + x] = t[x][y + j];
}

// ---------------- feasC1 (+ efea gather): per-bt block ----------------
__global__ void feasC1_kernel(const float* __restrict__ xs, const int* __restrict__ spans,
                              const float* __restrict__ Ww, const float* __restrict__ bw,
                              const float* __restrict__ Wa) {
    int bt = blockIdx.x;           // 32 blocks, 256 threads
    int b = bt >> 1;
    int tid = threadIdx.x;
    int span = spans[bt];
    __shared__ float s_e[CE * CH];     // 24KB
    __shared__ float s_f[CH];
    __shared__ float s_r[4];
    float4* ep = reinterpret_cast<float4*>(&g_efea[bt * CE * CH]);
    #pragma unroll
    for (int j = 0; j < 6; j++) {
        int f = j * 256 + tid;             // over 1536 float4
        int e = f / 192, c4 = f % 192;
        float4 v = *reinterpret_cast<const float4*>(
            &xs[((long long)b * CS + span + e) * CH + c4 * 4]);
        reinterpret_cast<float4*>(s_e)[f] = v;
        ep[f] = v;
    }
    __syncthreads();
    for (int h = tid; h < CH; h += 256) {
        float a = 0.f;
        #pragma unroll
        for (int e = 0; e < CE; e++) a += s_e[e * CH + h];
        s_f[h] = a * (1.0f / CE);
    }
    __syncthreads();
    if (tid < 128) {
        float acc = bw[tid];
        for (int h = 0; h < CH; h++) acc += s_f[h] * Ww[h * CA + tid];
        float part = acc * Wa[tid];
        #pragma unroll
        for (int off = 16; off; off >>= 1) part += __shfl_xor_sync(0xffffffffu, part, off);
        if ((tid & 31) == 0) s_r[tid >> 5] = part;
    }
    __syncthreads();
    if (tid == 0) g_c1[bt] = s_r[0] + s_r[1] + s_r[2] + s_r[3];
}

// ---------------- stage B (vectorized): per-neighbor SDPA + messages + score ----------------
#define KCP (CD + 4)   // 132-word pitch: stride ≡ 4 (mod 32) -> LDS.128 phase-conflict-free
__global__ void stageB_kernel(const float* __restrict__ neigh, const float* __restrict__ dists,
                              const float* __restrict__ Ww, const float* __restrict__ bw,
                              const float* __restrict__ Wa, const float* __restrict__ ba,
                              const float* __restrict__ wb, const float* __restrict__ bb) {
    int bid = blockIdx.x;                 // B*T*N = 1024 blocks, 256 threads
    int bt = bid / CN, n = bid % CN;
    int tid = threadIdx.x;
    const float inv_sqrt_d = 0.08838834764831845f;

    __shared__ float s_q[CE * CD];        // 4KB; aliased as red4 after logits
    __shared__ float s_kc[CL * KCP];      // 33KB
    __shared__ float s_attn[CE * CL];     // 2KB
    __shared__ float s_pooled[CH];        // 3KB
    __shared__ float s_red[256];          // 1KB

    // load q: 256 float4, 1 per thread
    reinterpret_cast<float4*>(s_q)[tid] =
        reinterpret_cast<const float4*>(&g_qe[bt * CE * CD])[tid];
    // load k tile 64x128: 2048 float4, 8 per thread
    {
        const float4* kp = reinterpret_cast<const float4*>(&g_kbuf[(long long)bid * CL * CD]);
        #pragma unroll
        for (int j = 0; j < 8; j++) {
            int f = j * 256 + tid;
            int l = f >> 5, c4 = f & 31;
            *reinterpret_cast<float4*>(&s_kc[l * KCP + c4 * 4]) = kp[f];
        }
    }
    __syncthreads();

    // logits: 512 outputs, 2 per thread, float4 over d
    #pragma unroll
    for (int r = 0; r < 2; r++) {
        int o = r * 256 + tid;
        int e = o >> 6, l = o & 63;
        const float4* q4 = reinterpret_cast<const float4*>(&s_q[e * CD]);
        const float4* k4 = reinterpret_cast<const float4*>(&s_kc[l * KCP]);
        float acc = 0.f;
        #pragma unroll 8
        for (int d = 0; d < 32; d++) {
            float4 a = q4[d], b = k4[d];
            acc += a.x * b.x + a.y * b.y + a.z * b.z + a.w * b.w;
        }
        s_attn[o] = acc * inv_sqrt_d;
    }
    __syncthreads();

    // softmax over l: one warp per row e
    {
        int w = tid >> 5, lane = tid & 31;
        if (w < CE) {
            float v1 = s_attn[w * CL + lane], v2 = s_attn[w * CL + lane + 32];
            float m = fmaxf(v1, v2);
            #pragma unroll
            for (int off = 16; off; off >>= 1) m = fmaxf(m, __shfl_xor_sync(0xffffffffu, m, off));
            float e1 = __expf(v1 - m), e2 = __expf(v2 - m);
            float s = e1 + e2;
            #pragma unroll
            for (int off = 16; off; off >>= 1) s += __shfl_xor_sync(0xffffffffu, s, off);
            float inv = 1.0f / s;
            s_attn[w * CL + lane] = e1 * inv;
            s_attn[w * CL + lane + 32] = e2 * inv;
        }
    }
    __syncthreads();

    // msgs = attn @ neigh, 6 chunks of 128 h; each thread owns (e = tid>>5, jg = tid&31)
    float* s_red4 = s_q;   // alias (q only needed for logits)
    const long long nb = ((long long)bid) * CL * CH;
    const long long mb = ((long long)bid) * CE * CH;
    int e = tid >> 5, jg = tid & 31;
    for (int hc = 0; hc < CH; hc += 128) {
        #pragma unroll
        for (int j = 0; j < 8; j++) {
            int f = j * 256 + tid;
            int l = f >> 5, c4 = f & 31;
            *reinterpret_cast<float4*>(&s_kc[l * KCP + c4 * 4]) =
                *reinterpret_cast<const float4*>(&neigh[nb + (long long)l * CH + hc + c4 * 4]);
        }
        __syncthreads();
        float4 acc = {0.f, 0.f, 0.f, 0.f};
        const float* at = &s_attn[e * CL];
        #pragma unroll 16
        for (int l = 0; l < CL; l++) {
            float a = at[l];
            float4 k = *reinterpret_cast<const float4*>(&s_kc[l * KCP + jg * 4]);
            acc.x += a * k.x; acc.y += a * k.y; acc.z += a * k.z; acc.w += a * k.w;
        }
        *reinterpret_cast<float4*>(&g_msgs[mb + (long long)e * CH + hc + jg * 4]) = acc;
        *reinterpret_cast<float4*>(&s_red4[tid * 4]) = acc;
        __syncthreads();
        if (tid < 128) {
            int jg2 = tid >> 2, comp = tid & 3;
            float s = 0.f;
            #pragma unroll
            for (int e2 = 0; e2 < CE; e2++) s += s_red4[(e2 * 32 + jg2) * 4 + comp];
            s_pooled[hc + tid] = s * (1.0f / CE);
        }
        __syncthreads();
    }

    // wp = pooled@Ww + bw ; dot with Wa[A:2A]; score
    float part = 0.f;
    if (tid < CA) {
        float acc = bw[tid];
        for (int h = 0; h < CH; h++) acc += s_pooled[h] * Ww[h * CA + tid];
        part = acc * Wa[CA + tid];
    }
    s_red[tid] = part;
    __syncthreads();
    for (int s = 128; s > 0; s >>= 1) {
        if (tid < s) s_red[tid] += s_red[tid + s];
        __syncthreads();
    }
    if (tid == 0) {
        float v = g_c1[bt] + s_red[0] + ba[0];
        v = (v > 0.f) ? v : 0.01f * v;
        v += dists[bt * CN + n] * wb[0] + bb[0];
        g_score[bt * CN + n] = 1.0f / (1.0f + __expf(-v));
    }
}

// ---------------- copy xs -> x ----------------
__global__ void copy_kernel(const float* __restrict__ xs) {
    long long i = (long long)blockIdx.x * blockDim.x + threadIdx.x;
    const long long n4 = (long long)CB * CS * CH / 4;
    if (i < n4) reinterpret_cast<float4*>(g_x)[i] = reinterpret_cast<const float4*>(xs)[i];
}

// ---------------- scatter delta into spans (one t per launch) ----------------
__global__ void scatter_kernel(const int* __restrict__ spans, int t) {
    int i = blockIdx.x * blockDim.x + threadIdx.x;
    if (i >= CB * CE * CH) return;
    int b = i / (CE * CH);
    int r = i % (CE * CH);
    int e = r / CH, h = r % CH;
    int bt = b * CT + t;
    float val = 0.f;
    const float* sc = &g_score[bt * CN];
    const float* ms = &g_msgs[(((long long)bt * CN) * CE + e) * CH + h];
    #pragma unroll 8
    for (int n = 0; n < CN; n++) val += sc[n] * ms[(long long)n * CE * CH];
    int span = spans[bt];
    g_x[((long long)b * CS + span + e) * CH + h] += val;
}

// ---------------- row softmax for s2 ----------------
__global__ void softmax_kernel() {
    int row = blockIdx.x;
    int tid = threadIdx.x;
    float* p = &g_s2[(long long)row * CS];
    __shared__ float s_red[256];
    float v1 = p[tid], v2 = p[tid + 256];
    float m = fmaxf(v1, v2);
    s_red[tid] = m;
    __syncthreads();
    for (int s = 128; s > 0; s >>= 1) { if (tid < s) s_red[tid] = fmaxf(s_red[tid], s_red[tid + s]); __syncthreads(); }
    m = s_red[0];
    __syncthreads();
    float e1 = __expf(v1 - m), e2 = __expf(v2 - m);
    s_red[tid] = e1 + e2;
    __syncthreads();
    for (int s = 128; s > 0; s >>= 1) { if (tid < s) s_red[tid] += s_red[tid + s]; __syncthreads(); }
    float inv = 1.0f / s_red[0];
    p[tid] = e1 * inv;
    p[tid + 256] = e2 * inv;
}

// ---------------- host ----------------
extern "C" void kernel_launch(void* const* d_in, const int* in_sizes, int n_in,
                              void* d_out, int out_size) {
    const float* xs    = (const float*)d_in[0];
    const float* neigh = (const float*)d_in[1];
    const float* dists = (const float*)d_in[2];
    const int*   spans = (const int*)d_in[3];
    const float* Wq = (const float*)d_in[4];
    const float* bq = (const float*)d_in[5];
    const float* Wk = (const float*)d_in[6];
    const float* bk = (const float*)d_in[7];
    const float* Wv = (const float*)d_in[8];
    const float* bv = (const float*)d_in[9];
    const float* Ww = (const float*)d_in[10];
    const float* bw = (const float*)d_in[11];
    const float* Wa = (const float*)d_in[12];
    const float* ba = (const float*)d_in[13];
    const float* wb = (const float*)d_in[14];
    const float* bb = (const float*)d_in[15];
    float* out = (float*)d_out;

    float *kbuf, *x, *qk2, *v2T, *s2, *wqkT, *wvT, *bqk, *efea, *qe;
    cudaGetSymbolAddress((void**)&kbuf, g_kbuf);
    cudaGetSymbolAddress((void**)&x,    g_x);
    cudaGetSymbolAddress((void**)&qk2,  g_qk2);
    cudaGetSymbolAddress((void**)&v2T,  g_v2T);
    cudaGetSymbolAddress((void**)&s2,   g_s2);
    cudaGetSymbolAddress((void**)&wqkT, g_wqkT);
    cudaGetSymbolAddress((void**)&wvT,  g_wvT);
    cudaGetSymbolAddress((void**)&bqk,  g_bqk);
    cudaGetSymbolAddress((void**)&efea, g_efea);
    cudaGetSymbolAddress((void**)&qe,   g_qe);

    cudaFuncSetAttribute(mm_gemm_kernel, cudaFuncAttributeMaxDynamicSharedMemorySize, GE_SMEM_BYTES);

    const float inv_sqrt_d = 0.08838834764831845f;

    // all weight prep in one launch
    prep_kernel<<<769, dim3(32, 8)>>>(Wq, Wk, Wv, bq, bk);

    // entity features: gather + feas/c1 (writes g_efea), then qe via GEMM
    feasC1_kernel<<<CB * CT, 256>>>(xs, spans, Ww, bw, Wa);
    mm_gemm_kernel<<<dim3(1, 2, 1), 256, GE_SMEM_BYTES>>>(
        efea, wqkT, bq, qe, CB*CT*CE, CD, CH, 1.0f, CH, CH, CD, 1, 0, 0, 0);

    // k projection: [65536,768] @ WkT^T -> [65536,128]
    mm_gemm_kernel<<<dim3(1, 512, 1), 256, GE_SMEM_BYTES>>>(
        neigh, wqkT + CD * CH, bk, kbuf, CB*CT*CN*CL, CD, CH, 1.0f, CH, CH, CD, 1, 0, 0, 0);

    // per-neighbor SDPA + messages + scores
    stageB_kernel<<<CB * CT * CN, 256>>>(neigh, dists, Ww, bw, Wa, ba, wb, bb);

    // x = xs; scatter deltas (t=0, t=1 sequential: deterministic)
    copy_kernel<<<(CB * CS * CH / 4 + 255) / 256, 256>>>(xs);
    scatter_kernel<<<(CB * CE * CH + 255) / 256, 256>>>(spans, 0);
    scatter_kernel<<<(CB * CE * CH + 255) / 256, 256>>>(spans, 1);

    // fused q2|k2 projection: [8192,768] @ wqkT^T -> [8192,256]
    mm_gemm_kernel<<<dim3(2, 64, 1), 256, GE_SMEM_BYTES>>>(
        x, wqkT, bqk, qk2, CB * CS, 2 * CD, CH, 1.0f, CH, CH, 2 * CD, 1, 0, 0, 0);

    // v2T = wvT @ x^T per batch: [768,512], row-bias bv
    mm_gemm_kernel<<<dim3(4, 6, CB), 256, GE_SMEM_BYTES>>>(
        wvT, x, bv, v2T, CH, CS, CH, 1.0f, CH, CH, CS, 2,
        0, (long long)CS * CH, (long long)CH * CS);

    // s2 = q2 @ k2^T * inv_sqrt_d (batched; q2/k2 interleaved in qk2)
    mm_gemm_kernel<<<dim3(4, 4, CB), 256, GE_SMEM_BYTES>>>(
        qk2, qk2 + CD, nullptr, s2, CS, CS, CD, inv_sqrt_d, 2 * CD, 2 * CD, CS, 0,
        (long long)CS * 2 * CD, (long long)CS * 2 * CD, (long long)CS * CS);

    softmax_kernel<<<CB * CS, 256>>>();

    // out = softmax(s2) @ v2  (B operand = v2T [768,512], batched)
    mm_gemm_kernel<<<dim3(6, 4, CB), 256, GE_SMEM_BYTES>>>(
        s2, v2T, nullptr, out, CS, CH, CS, 1.0f, CS, CS, CH, 0,
        (long long)CS * CS, (long long)CH * CS, (long long)CS * CH);
}

// round 10
// speedup vs baseline: 1.1731x; 1.0170x over previous
#include <cuda_runtime.h>
#include <math.h>
#include <stdint.h>

// Problem constants
#define CB 16
#define CS 512
#define CH 768
#define CT 2
#define CN 32
#define CL 64
#define CE 8
#define CD 128
#define CA 128

// ---------------- scratch (device globals; no allocation allowed) ----------------
__device__ float g_kbuf[CB*CT*CN*CL*CD];       // neighbor k projections
__device__ float g_msgs[CB*CT*CN*CE*CH];       // per-neighbor messages
__device__ float g_score[CB*CT*CN];
__device__ float g_c1[CB*CT];
__device__ float g_qe[CB*CT*CE*CD];
__device__ float g_efea[CB*CT*CE*CH];          // gathered entity span features [256,768]
__device__ float g_x[CB*CS*CH];
__device__ float g_qk2[CB*CS*2*CD];            // fused q2|k2 [B*S, 256]
__device__ float g_v2T[CB*CH*CS];              // v2 transposed per batch [B][768][512]
__device__ float g_s2[CB*CS*CS];
__device__ float g_wqkT[2*CD*CH];              // [WqT; WkT] [256,768]
__device__ float g_wvT[CH*CH];
__device__ float g_bqk[2*CD];

// ================= tf32 mma.sync GEMM (CTA 128x128, warp 32x64, single-sync pipeline) =====
// A [M,K] rows lda, B [N,K] rows ldb, C [M,N] rows ldc. M,N mult 128, K mult 32.
// bias_mode: 0 none, 1 per-col, 2 per-row. Batched via blockIdx.z (strides sA,sB,sC).

#define GE_SMEM_BYTES 65536

__device__ __forceinline__ void mma_tf32(float c[4], const uint32_t a[4], const uint32_t b[2]) {
    asm volatile(
        "mma.sync.aligned.m16n8k8.row.col.f32.tf32.tf32.f32 "
        "{%0,%1,%2,%3}, {%4,%5,%6,%7}, {%8,%9}, {%0,%1,%2,%3};"
        : "+f"(c[0]), "+f"(c[1]), "+f"(c[2]), "+f"(c[3])
        : "r"(a[0]), "r"(a[1]), "r"(a[2]), "r"(a[3]), "r"(b[0]), "r"(b[1]));
}

__device__ __forceinline__ void tile_ldg(const float* __restrict__ p, int lda, int tid, float4 r[4]) {
    #pragma unroll
    for (int j = 0; j < 4; j++) {
        int f = j * 256 + tid;
        int row = f >> 3, c4 = f & 7;
        float4 v = *reinterpret_cast<const float4*>(p + (long long)row * lda + c4 * 4);
        asm volatile("cvt.rna.tf32.f32 %0, %0;" : "+r"(*(uint32_t*)&v.x));
        asm volatile("cvt.rna.tf32.f32 %0, %0;" : "+r"(*(uint32_t*)&v.y));
        asm volatile("cvt.rna.tf32.f32 %0, %0;" : "+r"(*(uint32_t*)&v.z));
        asm volatile("cvt.rna.tf32.f32 %0, %0;" : "+r"(*(uint32_t*)&v.w));
        r[j] = v;
    }
}

__device__ __forceinline__ void sts_fragA(float* sm, int tid, const float4 r[4]) {
    #pragma unroll
    for (int j = 0; j < 4; j++) {
        int f = j * 256 + tid;
        int row = f >> 3, c4 = f & 7;
        int ks = c4 >> 1;
        int jfrag = ((row >> 3) & 1) + ((c4 & 1) << 1);
        int mt = row >> 4, g = row & 7;
        float* base = sm + (((ks * 8 + mt) * 32 + g * 4) << 2) + jfrag;
        const float* v = reinterpret_cast<const float*>(&r[j]);
        #pragma unroll
        for (int t = 0; t < 4; t++) base[t << 2] = v[t];
    }
}

__device__ __forceinline__ void sts_fragB(float* sm, int tid, const float4 r[4]) {
    #pragma unroll
    for (int j = 0; j < 4; j++) {
        int f = j * 256 + tid;
        int row = f >> 3, c4 = f & 7;
        int ks = c4 >> 1;
        int jfrag = c4 & 1;
        int nt = row >> 3, g = row & 7;
        float* base = sm + (((ks * 16 + nt) * 32 + g * 4) << 1) + jfrag;
        const float* v = reinterpret_cast<const float*>(&r[j]);
        #pragma unroll
        for (int t = 0; t < 4; t++) base[t << 1] = v[t];
    }
}

__global__ void __launch_bounds__(256)
mm_gemm_kernel(const float* __restrict__ A, const float* __restrict__ B,
               const float* __restrict__ bias, float* __restrict__ C,
               int M, int N, int K, float alpha,
               int lda, int ldb, int ldc, int bias_mode,
               long long sA, long long sB, long long sC)
{
    extern __shared__ float smem[];
    float* smA[2] = { smem,          smem + 8192 };
    float* smB[2] = { smem + 4096,   smem + 12288 };

    int tid = threadIdx.x;
    int wid = tid >> 5, lane = tid & 31;
    int warpM = wid & 3;
    int warpN = wid >> 2;

    const float* Ab = A + (long long)blockIdx.z * sA + (long long)(blockIdx.y * 128) * lda;
    const float* Bb = B + (long long)blockIdx.z * sB + (long long)(blockIdx.x * 128) * ldb;

    float acc[2][8][4];
    #pragma unroll
    for (int i = 0; i < 2; i++)
        #pragma unroll
        for (int j = 0; j < 8; j++)
            #pragma unroll
            for (int c = 0; c < 4; c++) acc[i][j][c] = 0.f;

    int nch = K >> 5;
    float4 ra[4], rb[4];
    tile_ldg(Ab, lda, tid, ra);
    tile_ldg(Bb, ldb, tid, rb);
    sts_fragA(smA[0], tid, ra);
    sts_fragB(smB[0], tid, rb);

    // single-sync pipeline: sync -> LDG(i+1) -> MMA(i) -> STS(i+1)
    for (int i = 0; i < nch; i++) {
        int buf = i & 1;
        __syncthreads();
        bool more = (i + 1 < nch);
        if (more) {
            tile_ldg(Ab + (i + 1) * 32, lda, tid, ra);
            tile_ldg(Bb + (i + 1) * 32, ldb, tid, rb);
        }
        const float* fA = smA[buf] + ((warpM * 2) * 32 + lane) * 4;
        const float* fB = smB[buf] + ((warpN * 8) * 32 + lane) * 2;
        #pragma unroll
        for (int ks = 0; ks < 4; ks++) {
            uint32_t afr[2][4];
            #pragma unroll
            for (int mt = 0; mt < 2; mt++) {
                float4 v = *reinterpret_cast<const float4*>(fA + (ks * 8 + mt) * 128);
                afr[mt][0] = __float_as_uint(v.x); afr[mt][1] = __float_as_uint(v.y);
                afr[mt][2] = __float_as_uint(v.z); afr[mt][3] = __float_as_uint(v.w);
            }
            #pragma unroll
            for (int nt = 0; nt < 8; nt++) {
                float2 v = *reinterpret_cast<const float2*>(fB + (ks * 16 + nt) * 64);
                uint32_t bfr[2] = { __float_as_uint(v.x), __float_as_uint(v.y) };
                mma_tf32(acc[0][nt], afr[0], bfr);
                mma_tf32(acc[1][nt], afr[1], bfr);
            }
        }
        if (more) {
            sts_fragA(smA[buf ^ 1], tid, ra);
            sts_fragB(smB[buf ^ 1], tid, rb);
        }
    }

    int g = lane >> 2, t = lane & 3;
    long long crow0 = (long long)(blockIdx.y * 128 + warpM * 32 + g);
    int col0 = blockIdx.x * 128 + warpN * 64 + t * 2;
    float* Cb = C + (long long)blockIdx.z * sC;
    #pragma unroll
    for (int mt = 0; mt < 2; mt++) {
        long long r0 = crow0 + mt * 16;
        float br0 = 0.f, br1 = 0.f;
        if (bias_mode == 2) { br0 = bias[r0]; br1 = bias[r0 + 8]; }
        #pragma unroll
        for (int nt = 0; nt < 8; nt++) {
            int cc = col0 + nt * 8;
            float bcx = 0.f, bcy = 0.f;
            if (bias_mode == 1) { bcx = bias[cc]; bcy = bias[cc + 1]; }
            float2 v0 = { acc[mt][nt][0] * alpha + bcx + br0, acc[mt][nt][1] * alpha + bcy + br0 };
            float2 v1 = { acc[mt][nt][2] * alpha + bcx + br1, acc[mt][nt][3] * alpha + bcy + br1 };
            *reinterpret_cast<float2*>(Cb + r0 * ldc + cc) = v0;
            *reinterpret_cast<float2*>(Cb + (r0 + 8) * ldc + cc) = v1;
        }
    }
}

// ---------------- prep: all weight transposes + bias pack in ONE launch ----------------
__global__ void prep_kernel(const float* __restrict__ Wq, const float* __restrict__ Wk,
                            const float* __restrict__ Wv,
                            const float* __restrict__ bq, const float* __restrict__ bk) {
    int bid = blockIdx.x;
    int x = threadIdx.x, y = threadIdx.y;      // 32 x 8
    if (bid == 768) {
        int i = y * 32 + x;
        g_bqk[i] = (i < CD) ? bq[i] : bk[i - CD];
        return;
    }
    const float* src; float* dst; int R, C, tile;
    if (bid < 96)       { src = Wq; dst = g_wqkT;            R = CH; C = CD; tile = bid; }
    else if (bid < 192) { src = Wk; dst = g_wqkT + CD * CH;  R = CH; C = CD; tile = bid - 96; }
    else                { src = Wv; dst = g_wvT;             R = CH; C = CH; tile = bid - 192; }
    int tcols = C >> 5;
    int c0 = (tile % tcols) * 32, r0 = (tile / tcols) * 32;
    __shared__ float t[32][33];
    #pragma unroll
    for (int j = 0; j < 32; j += 8)
        t[y + j][x] = src[(long long)(r0 + y + j) * C + c0 + x];
    __syncthreads();
    #pragma unroll
    for (int j = 0; j < 32; j += 8)
        dst[(long long)(c0 + y + j) * R + r0 + x] = t[x][y + j];
}

// ---------------- feasC1 (+ efea gather): per-bt block ----------------
__global__ void feasC1_kernel(const float* __restrict__ xs, const int* __restrict__ spans,
                              const float* __restrict__ Ww, const float* __restrict__ bw,
                              const float* __restrict__ Wa) {
    int bt = blockIdx.x;           // 32 blocks, 256 threads
    int b = bt >> 1;
    int tid = threadIdx.x;
    int span = spans[bt];
    __shared__ float s_e[CE * CH];     // 24KB
    __shared__ float s_f[CH];
    __shared__ float s_r[4];
    float4* ep = reinterpret_cast<float4*>(&g_efea[bt * CE * CH]);
    #pragma unroll
    for (int j = 0; j < 6; j++) {
        int f = j * 256 + tid;             // over 1536 float4
        int e = f / 192, c4 = f % 192;
        float4 v = *reinterpret_cast<const float4*>(
            &xs[((long long)b * CS + span + e) * CH + c4 * 4]);
        reinterpret_cast<float4*>(s_e)[f] = v;
        ep[f] = v;
    }
    __syncthreads();
    for (int h = tid; h < CH; h += 256) {
        float a = 0.f;
        #pragma unroll
        for (int e = 0; e < CE; e++) a += s_e[e * CH + h];
        s_f[h] = a * (1.0f / CE);
    }
    __syncthreads();
    if (tid < 128) {
        float acc = bw[tid];
        for (int h = 0; h < CH; h++) acc += s_f[h] * Ww[h * CA + tid];
        float part = acc * Wa[tid];
        #pragma unroll
        for (int off = 16; off; off >>= 1) part += __shfl_xor_sync(0xffffffffu, part, off);
        if ((tid & 31) == 0) s_r[tid >> 5] = part;
    }
    __syncthreads();
    if (tid == 0) g_c1[bt] = s_r[0] + s_r[1] + s_r[2] + s_r[3];
}

// ---------------- stage B (vectorized): per-neighbor SDPA + messages + score ----------------
#define KCP (CD + 4)   // 132-word pitch
__global__ void stageB_kernel(const float* __restrict__ neigh, const float* __restrict__ dists,
                              const float* __restrict__ Ww, const float* __restrict__ bw,
                              const float* __restrict__ Wa, const float* __restrict__ ba,
                              const float* __restrict__ wb, const float* __restrict__ bb) {
    int bid = blockIdx.x;                 // B*T*N = 1024 blocks, 256 threads
    int bt = bid / CN, n = bid % CN;
    int tid = threadIdx.x;
    const float inv_sqrt_d = 0.08838834764831845f;

    __shared__ float s_q[CE * CD];        // 4KB; aliased as red4 after logits
    __shared__ float s_kc[CL * KCP];      // 33KB
    __shared__ float s_attn[CE * CL];     // 2KB
    __shared__ float s_pooled[CH];        // 3KB
    __shared__ float s_red[256];          // 1KB

    reinterpret_cast<float4*>(s_q)[tid] =
        reinterpret_cast<const float4*>(&g_qe[bt * CE * CD])[tid];
    {
        const float4* kp = reinterpret_cast<const float4*>(&g_kbuf[(long long)bid * CL * CD]);
        #pragma unroll
        for (int j = 0; j < 8; j++) {
            int f = j * 256 + tid;
            int l = f >> 5, c4 = f & 31;
            *reinterpret_cast<float4*>(&s_kc[l * KCP + c4 * 4]) = kp[f];
        }
    }
    __syncthreads();

    #pragma unroll
    for (int r = 0; r < 2; r++) {
        int o = r * 256 + tid;
        int e = o >> 6, l = o & 63;
        const float4* q4 = reinterpret_cast<const float4*>(&s_q[e * CD]);
        const float4* k4 = reinterpret_cast<const float4*>(&s_kc[l * KCP]);
        float acc = 0.f;
        #pragma unroll 8
        for (int d = 0; d < 32; d++) {
            float4 a = q4[d], b = k4[d];
            acc += a.x * b.x + a.y * b.y + a.z * b.z + a.w * b.w;
        }
        s_attn[o] = acc * inv_sqrt_d;
    }
    __syncthreads();

    {
        int w = tid >> 5, lane = tid & 31;
        if (w < CE) {
            float v1 = s_attn[w * CL + lane], v2 = s_attn[w * CL + lane + 32];
            float m = fmaxf(v1, v2);
            #pragma unroll
            for (int off = 16; off; off >>= 1) m = fmaxf(m, __shfl_xor_sync(0xffffffffu, m, off));
            float e1 = __expf(v1 - m), e2 = __expf(v2 - m);
            float s = e1 + e2;
            #pragma unroll
            for (int off = 16; off; off >>= 1) s += __shfl_xor_sync(0xffffffffu, s, off);
            float inv = 1.0f / s;
            s_attn[w * CL + lane] = e1 * inv;
            s_attn[w * CL + lane + 32] = e2 * inv;
        }
    }
    __syncthreads();

    float* s_red4 = s_q;   // alias
    const long long nb = ((long long)bid) * CL * CH;
    const long long mb = ((long long)bid) * CE * CH;
    int e = tid >> 5, jg = tid & 31;
    for (int hc = 0; hc < CH; hc += 128) {
        #pragma unroll
        for (int j = 0; j < 8; j++) {
            int f = j * 256 + tid;
            int l = f >> 5, c4 = f & 31;
            *reinterpret_cast<float4*>(&s_kc[l * KCP + c4 * 4]) =
                *reinterpret_cast<const float4*>(&neigh[nb + (long long)l * CH + hc + c4 * 4]);
        }
        __syncthreads();
        float4 acc = {0.f, 0.f, 0.f, 0.f};
        const float* at = &s_attn[e * CL];
        #pragma unroll 16
        for (int l = 0; l < CL; l++) {
            float a = at[l];
            float4 k = *reinterpret_cast<const float4*>(&s_kc[l * KCP + jg * 4]);
            acc.x += a * k.x; acc.y += a * k.y; acc.z += a * k.z; acc.w += a * k.w;
        }
        *reinterpret_cast<float4*>(&g_msgs[mb + (long long)e * CH + hc + jg * 4]) = acc;
        *reinterpret_cast<float4*>(&s_red4[tid * 4]) = acc;
        __syncthreads();
        if (tid < 128) {
            int jg2 = tid >> 2, comp = tid & 3;
            float s = 0.f;
            #pragma unroll
            for (int e2 = 0; e2 < CE; e2++) s += s_red4[(e2 * 32 + jg2) * 4 + comp];
            s_pooled[hc + tid] = s * (1.0f / CE);
        }
        __syncthreads();
    }

    float part = 0.f;
    if (tid < CA) {
        float acc = bw[tid];
        for (int h = 0; h < CH; h++) acc += s_pooled[h] * Ww[h * CA + tid];
        part = acc * Wa[CA + tid];
    }
    s_red[tid] = part;
    __syncthreads();
    for (int s = 128; s > 0; s >>= 1) {
        if (tid < s) s_red[tid] += s_red[tid + s];
        __syncthreads();
    }
    if (tid == 0) {
        float v = g_c1[bt] + s_red[0] + ba[0];
        v = (v > 0.f) ? v : 0.01f * v;
        v += dists[bt * CN + n] * wb[0] + bb[0];
        g_score[bt * CN + n] = 1.0f / (1.0f + __expf(-v));
    }
}

// ---------------- fused copy + scatter: x = xs, spans get score-weighted messages ----------------
__global__ void copy_scatter_kernel(const float* __restrict__ xs, const int* __restrict__ spans) {
    int i4 = blockIdx.x * blockDim.x + threadIdx.x;      // over B*S*H/4 = 1572864
    const int total4 = CB * CS * CH / 4;
    if (i4 >= total4) return;
    int f = i4 * 4;
    int b = f / (CS * CH);
    int r = f % (CS * CH);
    int s = r / CH, h = r % CH;
    float4 v = reinterpret_cast<const float4*>(xs)[i4];
    #pragma unroll
    for (int t = 0; t < 2; t++) {
        int bt = b * CT + t;
        int e = s - spans[bt];
        if (e >= 0 && e < CE) {
            const float* sc = &g_score[bt * CN];
            const float* ms = &g_msgs[(((long long)bt * CN) * CE + e) * CH + h];
            float4 d = {0.f, 0.f, 0.f, 0.f};
            #pragma unroll 8
            for (int n = 0; n < CN; n++) {
                float a = sc[n];
                float4 m = *reinterpret_cast<const float4*>(ms + (long long)n * CE * CH);
                d.x += a * m.x; d.y += a * m.y; d.z += a * m.z; d.w += a * m.w;
            }
            v.x += d.x; v.y += d.y; v.z += d.z; v.w += d.w;
        }
    }
    reinterpret_cast<float4*>(g_x)[i4] = v;
}

// ---------------- row softmax for s2 ----------------
__global__ void softmax_kernel() {
    int row = blockIdx.x;
    int tid = threadIdx.x;
    float* p = &g_s2[(long long)row * CS];
    __shared__ float s_red[256];
    float v1 = p[tid], v2 = p[tid + 256];
    float m = fmaxf(v1, v2);
    s_red[tid] = m;
    __syncthreads();
    for (int s = 128; s > 0; s >>= 1) { if (tid < s) s_red[tid] = fmaxf(s_red[tid], s_red[tid + s]); __syncthreads(); }
    m = s_red[0];
    __syncthreads();
    float e1 = __expf(v1 - m), e2 = __expf(v2 - m);
    s_red[tid] = e1 + e2;
    __syncthreads();
    for (int s = 128; s > 0; s >>= 1) { if (tid < s) s_red[tid] += s_red[tid + s]; __syncthreads(); }
    float inv = 1.0f / s_red[0];
    p[tid] = e1 * inv;
    p[tid + 256] = e2 * inv;
}

// ---------------- host ----------------
extern "C" void kernel_launch(void* const* d_in, const int* in_sizes, int n_in,
                              void* d_out, int out_size) {
    const float* xs    = (const float*)d_in[0];
    const float* neigh = (const float*)d_in[1];
    const float* dists = (const float*)d_in[2];
    const int*   spans = (const int*)d_in[3];
    const float* Wq = (const float*)d_in[4];
    const float* bq = (const float*)d_in[5];
    const float* Wk = (const float*)d_in[6];
    const float* bk = (const float*)d_in[7];
    const float* Wv = (const float*)d_in[8];
    const float* bv = (const float*)d_in[9];
    const float* Ww = (const float*)d_in[10];
    const float* bw = (const float*)d_in[11];
    const float* Wa = (const float*)d_in[12];
    const float* ba = (const float*)d_in[13];
    const float* wb = (const float*)d_in[14];
    const float* bb = (const float*)d_in[15];
    float* out = (float*)d_out;

    float *kbuf, *x, *qk2, *v2T, *s2, *wqkT, *wvT, *bqk, *efea, *qe;
    cudaGetSymbolAddress((void**)&kbuf, g_kbuf);
    cudaGetSymbolAddress((void**)&x,    g_x);
    cudaGetSymbolAddress((void**)&qk2,  g_qk2);
    cudaGetSymbolAddress((void**)&v2T,  g_v2T);
    cudaGetSymbolAddress((void**)&s2,   g_s2);
    cudaGetSymbolAddress((void**)&wqkT, g_wqkT);
    cudaGetSymbolAddress((void**)&wvT,  g_wvT);
    cudaGetSymbolAddress((void**)&bqk,  g_bqk);
    cudaGetSymbolAddress((void**)&efea, g_efea);
    cudaGetSymbolAddress((void**)&qe,   g_qe);

    cudaFuncSetAttribute(mm_gemm_kernel, cudaFuncAttributeMaxDynamicSharedMemorySize, GE_SMEM_BYTES);

    const float inv_sqrt_d = 0.08838834764831845f;

    // all weight prep in one launch
    prep_kernel<<<769, dim3(32, 8)>>>(Wq, Wk, Wv, bq, bk);

    // entity features: gather + feas/c1 (writes g_efea), then qe via GEMM
    feasC1_kernel<<<CB * CT, 256>>>(xs, spans, Ww, bw, Wa);
    mm_gemm_kernel<<<dim3(1, 2, 1), 256, GE_SMEM_BYTES>>>(
        efea, wqkT, bq, qe, CB*CT*CE, CD, CH, 1.0f, CH, CH, CD, 1, 0, 0, 0);

    // k projection: [65536,768] @ WkT^T -> [65536,128]
    mm_gemm_kernel<<<dim3(1, 512, 1), 256, GE_SMEM_BYTES>>>(
        neigh, wqkT + CD * CH, bk, kbuf, CB*CT*CN*CL, CD, CH, 1.0f, CH, CH, CD, 1, 0, 0, 0);

    // per-neighbor SDPA + messages + scores
    stageB_kernel<<<CB * CT * CN, 256>>>(neigh, dists, Ww, bw, Wa, ba, wb, bb);

    // x = xs + scattered deltas (fused, overlap-safe)
    copy_scatter_kernel<<<(CB * CS * CH / 4 + 255) / 256, 256>>>(xs, spans);

    // fused q2|k2 projection: [8192,768] @ wqkT^T -> [8192,256]
    mm_gemm_kernel<<<dim3(2, 64, 1), 256, GE_SMEM_BYTES>>>(
        x, wqkT, bqk, qk2, CB * CS, 2 * CD, CH, 1.0f, CH, CH, 2 * CD, 1, 0, 0, 0);

    // v2T = wvT @ x^T per batch: [768,512], row-bias bv
    mm_gemm_kernel<<<dim3(4, 6, CB), 256, GE_SMEM_BYTES>>>(
        wvT, x, bv, v2T, CH, CS, CH, 1.0f, CH, CH, CS, 2,
        0, (long long)CS * CH, (long long)CH * CS);

    // s2 = q2 @ k2^T * inv_sqrt_d (batched; q2/k2 interleaved in qk2)
    mm_gemm_kernel<<<dim3(4, 4, CB), 256, GE_SMEM_BYTES>>>(
        qk2, qk2 + CD, nullptr, s2, CS, CS, CD, inv_sqrt_d, 2 * CD, 2 * CD, CS, 0,
        (long long)CS * 2 * CD, (long long)CS * 2 * CD, (long long)CS * CS);

    softmax_kernel<<<CB * CS, 256>>>();

    // out = softmax(s2) @ v2  (B operand = v2T [768,512], batched)
    mm_gemm_kernel<<<dim3(6, 4, CB), 256, GE_SMEM_BYTES>>>(
        s2, v2T, nullptr, out, CS, CH, CS, 1.0f, CS, CS, CH, 0,
        (long long)CS * CS, (long long)CH * CS, (long long)CS * CH);
}

// round 13
// speedup vs baseline: 1.3284x; 1.1324x over previous
#include <cuda_runtime.h>
#include <math.h>
#include <stdint.h>

// Problem constants
#define CB 16
#define CS 512
#define CH 768
#define CT 2
#define CN 32
#define CL 64
#define CE 8
#define CD 128
#define CA 128

// ---------------- scratch (device globals; no allocation allowed) ----------------
__device__ float g_kbuf[CB*CT*CN*CL*CD];       // neighbor k projections
__device__ float g_msgs[CB*CT*CN*CE*CH];       // per-neighbor messages
__device__ float g_score[CB*CT*CN];
__device__ float g_c1[CB*CT];
__device__ float g_qe[CB*CT*CE*CD];
__device__ float g_efea[CB*CT*CE*CH];          // gathered entity span features [256,768]
__device__ float g_x[CB*CS*CH];
__device__ float g_qk2[CB*CS*2*CD];            // fused q2|k2 [B*S, 256]
__device__ float g_v2T[CB*CH*CS];              // v2 transposed per batch [B][768][512]
__device__ float g_s2[CB*CS*CS];
__device__ float g_wqkT[2*CD*CH];              // [WqT; WkT] [256,768]
__device__ float g_wvT[CH*CH];
__device__ float g_bqk[2*CD];

// ================= tf32 mma.sync GEMM (CTA 128x128, warp 32x64, single-sync pipeline) =====
// A [M,K] rows lda, B [N,K] rows ldb, C [M,N] rows ldc. M,N mult 128, K mult 32.
// bias_mode: 0 none, 1 per-col, 2 per-row. Batched via blockIdx.z (strides sA,sB,sC).
// __launch_bounds__(256, 2): cap regs at 128 so 2 CTAs co-reside per SM (16 warps).

#define GE_SMEM_BYTES 65536

__device__ __forceinline__ void mma_tf32(float c[4], const uint32_t a[4], const uint32_t b[2]) {
    asm volatile(
        "mma.sync.aligned.m16n8k8.row.col.f32.tf32.tf32.f32 "
        "{%0,%1,%2,%3}, {%4,%5,%6,%7}, {%8,%9}, {%0,%1,%2,%3};"
        : "+f"(c[0]), "+f"(c[1]), "+f"(c[2]), "+f"(c[3])
        : "r"(a[0]), "r"(a[1]), "r"(a[2]), "r"(a[3]), "r"(b[0]), "r"(b[1]));
}

__device__ __forceinline__ void tile_ldg(const float* __restrict__ p, int lda, int tid, float4 r[4]) {
    #pragma unroll
    for (int j = 0; j < 4; j++) {
        int f = j * 256 + tid;
        int row = f >> 3, c4 = f & 7;
        float4 v = *reinterpret_cast<const float4*>(p + (long long)row * lda + c4 * 4);
        asm volatile("cvt.rna.tf32.f32 %0, %0;" : "+r"(*(uint32_t*)&v.x));
        asm volatile("cvt.rna.tf32.f32 %0, %0;" : "+r"(*(uint32_t*)&v.y));
        asm volatile("cvt.rna.tf32.f32 %0, %0;" : "+r"(*(uint32_t*)&v.z));
        asm volatile("cvt.rna.tf32.f32 %0, %0;" : "+r"(*(uint32_t*)&v.w));
        r[j] = v;
    }
}

__device__ __forceinline__ void sts_fragA(float* sm, int tid, const float4 r[4]) {
    #pragma unroll
    for (int j = 0; j < 4; j++) {
        int f = j * 256 + tid;
        int row = f >> 3, c4 = f & 7;
        int ks = c4 >> 1;
        int jfrag = ((row >> 3) & 1) + ((c4 & 1) << 1);
        int mt = row >> 4, g = row & 7;
        float* base = sm + (((ks * 8 + mt) * 32 + g * 4) << 2) + jfrag;
        const float* v = reinterpret_cast<const float*>(&r[j]);
        #pragma unroll
        for (int t = 0; t < 4; t++) base[t << 2] = v[t];
    }
}

__device__ __forceinline__ void sts_fragB(float* sm, int tid, const float4 r[4]) {
    #pragma unroll
    for (int j = 0; j < 4; j++) {
        int f = j * 256 + tid;
        int row = f >> 3, c4 = f & 7;
        int ks = c4 >> 1;
        int jfrag = c4 & 1;
        int nt = row >> 3, g = row & 7;
        float* base = sm + (((ks * 16 + nt) * 32 + g * 4) << 1) + jfrag;
        const float* v = reinterpret_cast<const float*>(&r[j]);
        #pragma unroll
        for (int t = 0; t < 4; t++) base[t << 1] = v[t];
    }
}

__global__ void __launch_bounds__(256, 2)
mm_gemm_kernel(const float* __restrict__ A, const float* __restrict__ B,
               const float* __restrict__ bias, float* __restrict__ C,
               int M, int N, int K, float alpha,
               int lda, int ldb, int ldc, int bias_mode,
               long long sA, long long sB, long long sC)
{
    extern __shared__ float smem[];
    float* smA[2] = { smem,          smem + 8192 };
    float* smB[2] = { smem + 4096,   smem + 12288 };

    int tid = threadIdx.x;
    int wid = tid >> 5, lane = tid & 31;
    int warpM = wid & 3;
    int warpN = wid >> 2;

    const float* Ab = A + (long long)blockIdx.z * sA + (long long)(blockIdx.y * 128) * lda;
    const float* Bb = B + (long long)blockIdx.z * sB + (long long)(blockIdx.x * 128) * ldb;

    float acc[2][8][4];
    #pragma unroll
    for (int i = 0; i < 2; i++)
        #pragma unroll
        for (int j = 0; j < 8; j++)
            #pragma unroll
            for (int c = 0; c < 4; c++) acc[i][j][c] = 0.f;

    int nch = K >> 5;
    float4 ra[4], rb[4];
    tile_ldg(Ab, lda, tid, ra);
    tile_ldg(Bb, ldb, tid, rb);
    sts_fragA(smA[0], tid, ra);
    sts_fragB(smB[0], tid, rb);

    // single-sync pipeline: sync -> LDG(i+1) -> MMA(i) -> STS(i+1)
    for (int i = 0; i < nch; i++) {
        int buf = i & 1;
        __syncthreads();
        bool more = (i + 1 < nch);
        if (more) {
            tile_ldg(Ab + (i + 1) * 32, lda, tid, ra);
            tile_ldg(Bb + (i + 1) * 32, ldb, tid, rb);
        }
        const float* fA = smA[buf] + ((warpM * 2) * 32 + lane) * 4;
        const float* fB = smB[buf] + ((warpN * 8) * 32 + lane) * 2;
        #pragma unroll
        for (int ks = 0; ks < 4; ks++) {
            uint32_t afr[2][4];
            #pragma unroll
            for (int mt = 0; mt < 2; mt++) {
                float4 v = *reinterpret_cast<const float4*>(fA + (ks * 8 + mt) * 128);
                afr[mt][0] = __float_as_uint(v.x); afr[mt][1] = __float_as_uint(v.y);
                afr[mt][2] = __float_as_uint(v.z); afr[mt][3] = __float_as_uint(v.w);
            }
            #pragma unroll
            for (int nt = 0; nt < 8; nt++) {
                float2 v = *reinterpret_cast<const float2*>(fB + (ks * 16 + nt) * 64);
                uint32_t bfr[2] = { __float_as_uint(v.x), __float_as_uint(v.y) };
                mma_tf32(acc[0][nt], afr[0], bfr);
                mma_tf32(acc[1][nt], afr[1], bfr);
            }
        }
        if (more) {
            sts_fragA(smA[buf ^ 1], tid, ra);
            sts_fragB(smB[buf ^ 1], tid, rb);
        }
    }

    int g = lane >> 2, t = lane & 3;
    long long crow0 = (long long)(blockIdx.y * 128 + warpM * 32 + g);
    int col0 = blockIdx.x * 128 + warpN * 64 + t * 2;
    float* Cb = C + (long long)blockIdx.z * sC;
    #pragma unroll
    for (int mt = 0; mt < 2; mt++) {
        long long r0 = crow0 + mt * 16;
        float br0 = 0.f, br1 = 0.f;
        if (bias_mode == 2) { br0 = bias[r0]; br1 = bias[r0 + 8]; }
        #pragma unroll
        for (int nt = 0; nt < 8; nt++) {
            int cc = col0 + nt * 8;
            float bcx = 0.f, bcy = 0.f;
            if (bias_mode == 1) { bcx = bias[cc]; bcy = bias[cc + 1]; }
            float2 v0 = { acc[mt][nt][0] * alpha + bcx + br0, acc[mt][nt][1] * alpha + bcy + br0 };
            float2 v1 = { acc[mt][nt][2] * alpha + bcx + br1, acc[mt][nt][3] * alpha + bcy + br1 };
            *reinterpret_cast<float2*>(Cb + r0 * ldc + cc) = v0;
            *reinterpret_cast<float2*>(Cb + (r0 + 8) * ldc + cc) = v1;
        }
    }
}

// ---------------- prep: all weight transposes + bias pack in ONE launch ----------------
__global__ void prep_kernel(const float* __restrict__ Wq, const float* __restrict__ Wk,
                            const float* __restrict__ Wv,
                            const float* __restrict__ bq, const float* __restrict__ bk) {
    int bid = blockIdx.x;
    int x = threadIdx.x, y = threadIdx.y;      // 32 x 8
    if (bid == 768) {
        int i = y * 32 + x;
        g_bqk[i] = (i < CD) ? bq[i] : bk[i - CD];
        return;
    }
    const float* src; float* dst; int R, C, tile;
    if (bid < 96)       { src = Wq; dst = g_wqkT;            R = CH; C = CD; tile = bid; }
    else if (bid < 192) { src = Wk; dst = g_wqkT + CD * CH;  R = CH; C = CD; tile = bid - 96; }
    else                { src = Wv; dst = g_wvT;             R = CH; C = CH; tile = bid - 192; }
    int tcols = C >> 5;
    int c0 = (tile % tcols) * 32, r0 = (tile / tcols) * 32;
    __shared__ float t[32][33];
    #pragma unroll
    for (int j = 0; j < 32; j += 8)
        t[y + j][x] = src[(long long)(r0 + y + j) * C + c0 + x];
    __syncthreads();
    #pragma unroll
    for (int j = 0; j < 32; j += 8)
        dst[(long long)(c0 + y + j) * R + r0 + x] = t[x][y + j];
}

// ---------------- feasC1 (+ efea gather): per-bt block ----------------
__global__ void feasC1_kernel(const float* __restrict__ xs, const int* __restrict__ spans,
                              const float* __restrict__ Ww, const float* __restrict__ bw,
                              const float* __restrict__ Wa) {
    int bt = blockIdx.x;           // 32 blocks, 256 threads
    int b = bt >> 1;
    int tid = threadIdx.x;
    int span = spans[bt];
    __shared__ float s_e[CE * CH];     // 24KB
    __shared__ float s_f[CH];
    __shared__ float s_r[4];
    float4* ep = reinterpret_cast<float4*>(&g_efea[bt * CE * CH]);
    #pragma unroll
    for (int j = 0; j < 6; j++) {
        int f = j * 256 + tid;             // over 1536 float4
        int e = f / 192, c4 = f % 192;
        float4 v = *reinterpret_cast<const float4*>(
            &xs[((long long)b * CS + span + e) * CH + c4 * 4]);
        reinterpret_cast<float4*>(s_e)[f] = v;
        ep[f] = v;
    }
    __syncthreads();
    for (int h = tid; h < CH; h += 256) {
        float a = 0.f;
        #pragma unroll
        for (int e = 0; e < CE; e++) a += s_e[e * CH + h];
        s_f[h] = a * (1.0f / CE);
    }
    __syncthreads();
    if (tid < 128) {
        float acc = bw[tid];
        for (int h = 0; h < CH; h++) acc += s_f[h] * Ww[h * CA + tid];
        float part = acc * Wa[tid];
        #pragma unroll
        for (int off = 16; off; off >>= 1) part += __shfl_xor_sync(0xffffffffu, part, off);
        if ((tid & 31) == 0) s_r[tid >> 5] = part;
    }
    __syncthreads();
    if (tid == 0) g_c1[bt] = s_r[0] + s_r[1] + s_r[2] + s_r[3];
}

// ---------------- stage B (vectorized): per-neighbor SDPA + messages + score ----------------
#define KCP (CD + 4)   // 132-word pitch
__global__ void stageB_kernel(const float* __restrict__ neigh, const float* __restrict__ dists,
                              const float* __restrict__ Ww, const float* __restrict__ bw,
                              const float* __restrict__ Wa, const float* __restrict__ ba,
                              const float* __restrict__ wb, const float* __restrict__ bb) {
    int bid = blockIdx.x;                 // B*T*N = 1024 blocks, 256 threads
    int bt = bid / CN, n = bid % CN;
    int tid = threadIdx.x;
    const float inv_sqrt_d = 0.08838834764831845f;

    __shared__ float s_q[CE * CD];        // 4KB; aliased as red4 after logits
    __shared__ float s_kc[CL * KCP];      // 33KB
    __shared__ float s_attn[CE * CL];     // 2KB
    __shared__ float s_pooled[CH];        // 3KB
    __shared__ float s_red[256];          // 1KB

    reinterpret_cast<float4*>(s_q)[tid] =
        reinterpret_cast<const float4*>(&g_qe[bt * CE * CD])[tid];
    {
        const float4* kp = reinterpret_cast<const float4*>(&g_kbuf[(long long)bid * CL * CD]);
        #pragma unroll
        for (int j = 0; j < 8; j++) {
            int f = j * 256 + tid;
            int l = f >> 5, c4 = f & 31;
            *reinterpret_cast<float4*>(&s_kc[l * KCP + c4 * 4]) = kp[f];
        }
    }
    __syncthreads();

    #pragma unroll
    for (int r = 0; r < 2; r++) {
        int o = r * 256 + tid;
        int e = o >> 6, l = o & 63;
        const float4* q4 = reinterpret_cast<const float4*>(&s_q[e * CD]);
        const float4* k4 = reinterpret_cast<const float4*>(&s_kc[l * KCP]);
        float acc = 0.f;
        #pragma unroll 8
        for (int d = 0; d < 32; d++) {
            float4 a = q4[d], b = k4[d];
            acc += a.x * b.x + a.y * b.y + a.z * b.z + a.w * b.w;
        }
        s_attn[o] = acc * inv_sqrt_d;
    }
    __syncthreads();

    {
        int w = tid >> 5, lane = tid & 31;
        if (w < CE) {
            float v1 = s_attn[w * CL + lane], v2 = s_attn[w * CL + lane + 32];
            float m = fmaxf(v1, v2);
            #pragma unroll
            for (int off = 16; off; off >>= 1) m = fmaxf(m, __shfl_xor_sync(0xffffffffu, m, off));
            float e1 = __expf(v1 - m), e2 = __expf(v2 - m);
            float s = e1 + e2;
            #pragma unroll
            for (int off = 16; off; off >>= 1) s += __shfl_xor_sync(0xffffffffu, s, off);
            float inv = 1.0f / s;
            s_attn[w * CL + lane] = e1 * inv;
            s_attn[w * CL + lane + 32] = e2 * inv;
        }
    }
    __syncthreads();

    float* s_red4 = s_q;   // alias
    const long long nb = ((long long)bid) * CL * CH;
    const long long mb = ((long long)bid) * CE * CH;
    int e = tid >> 5, jg = tid & 31;
    for (int hc = 0; hc < CH; hc += 128) {
        #pragma unroll
        for (int j = 0; j < 8; j++) {
            int f = j * 256 + tid;
            int l = f >> 5, c4 = f & 31;
            *reinterpret_cast<float4*>(&s_kc[l * KCP + c4 * 4]) =
                *reinterpret_cast<const float4*>(&neigh[nb + (long long)l * CH + hc + c4 * 4]);
        }
        __syncthreads();
        float4 acc = {0.f, 0.f, 0.f, 0.f};
        const float* at = &s_attn[e * CL];
        #pragma unroll 16
        for (int l = 0; l < CL; l++) {
            float a = at[l];
            float4 k = *reinterpret_cast<const float4*>(&s_kc[l * KCP + jg * 4]);
            acc.x += a * k.x; acc.y += a * k.y; acc.z += a * k.z; acc.w += a * k.w;
        }
        *reinterpret_cast<float4*>(&g_msgs[mb + (long long)e * CH + hc + jg * 4]) = acc;
        *reinterpret_cast<float4*>(&s_red4[tid * 4]) = acc;
        __syncthreads();
        if (tid < 128) {
            int jg2 = tid >> 2, comp = tid & 3;
            float s = 0.f;
            #pragma unroll
            for (int e2 = 0; e2 < CE; e2++) s += s_red4[(e2 * 32 + jg2) * 4 + comp];
            s_pooled[hc + tid] = s * (1.0f / CE);
        }
        __syncthreads();
    }

    float part = 0.f;
    if (tid < CA) {
        float acc = bw[tid];
        for (int h = 0; h < CH; h++) acc += s_pooled[h] * Ww[h * CA + tid];
        part = acc * Wa[CA + tid];
    }
    s_red[tid] = part;
    __syncthreads();
    for (int s = 128; s > 0; s >>= 1) {
        if (tid < s) s_red[tid] += s_red[tid + s];
        __syncthreads();
    }
    if (tid == 0) {
        float v = g_c1[bt] + s_red[0] + ba[0];
        v = (v > 0.f) ? v : 0.01f * v;
        v += dists[bt * CN + n] * wb[0] + bb[0];
        g_score[bt * CN + n] = 1.0f / (1.0f + __expf(-v));
    }
}

// ---------------- fused copy + scatter: x = xs, spans get score-weighted messages ----------------
__global__ void copy_scatter_kernel(const float* __restrict__ xs, const int* __restrict__ spans) {
    int i4 = blockIdx.x * blockDim.x + threadIdx.x;      // over B*S*H/4 = 1572864
    const int total4 = CB * CS * CH / 4;
    if (i4 >= total4) return;
    int f = i4 * 4;
    int b = f / (CS * CH);
    int r = f % (CS * CH);
    int s = r / CH, h = r % CH;
    float4 v = reinterpret_cast<const float4*>(xs)[i4];
    #pragma unroll
    for (int t = 0; t < 2; t++) {
        int bt = b * CT + t;
        int e = s - spans[bt];
        if (e >= 0 && e < CE) {
            const float* sc = &g_score[bt * CN];
            const float* ms = &g_msgs[(((long long)bt * CN) * CE + e) * CH + h];
            float4 d = {0.f, 0.f, 0.f, 0.f};
            #pragma unroll 8
            for (int n = 0; n < CN; n++) {
                float a = sc[n];
                float4 m = *reinterpret_cast<const float4*>(ms + (long long)n * CE * CH);
                d.x += a * m.x; d.y += a * m.y; d.z += a * m.z; d.w += a * m.w;
            }
            v.x += d.x; v.y += d.y; v.z += d.z; v.w += d.w;
        }
    }
    reinterpret_cast<float4*>(g_x)[i4] = v;
}

// ---------------- row softmax for s2 ----------------
__global__ void softmax_kernel() {
    int row = blockIdx.x;
    int tid = threadIdx.x;
    float* p = &g_s2[(long long)row * CS];
    __shared__ float s_red[256];
    float v1 = p[tid], v2 = p[tid + 256];
    float m = fmaxf(v1, v2);
    s_red[tid] = m;
    __syncthreads();
    for (int s = 128; s > 0; s >>= 1) { if (tid < s) s_red[tid] = fmaxf(s_red[tid], s_red[tid + s]); __syncthreads(); }
    m = s_red[0];
    __syncthreads();
    float e1 = __expf(v1 - m), e2 = __expf(v2 - m);
    s_red[tid] = e1 + e2;
    __syncthreads();
    for (int s = 128; s > 0; s >>= 1) { if (tid < s) s_red[tid] += s_red[tid + s]; __syncthreads(); }
    float inv = 1.0f / s_red[0];
    p[tid] = e1 * inv;
    p[tid + 256] = e2 * inv;
}

// ---------------- host ----------------
extern "C" void kernel_launch(void* const* d_in, const int* in_sizes, int n_in,
                              void* d_out, int out_size) {
    const float* xs    = (const float*)d_in[0];
    const float* neigh = (const float*)d_in[1];
    const float* dists = (const float*)d_in[2];
    const int*   spans = (const int*)d_in[3];
    const float* Wq = (const float*)d_in[4];
    const float* bq = (const float*)d_in[5];
    const float* Wk = (const float*)d_in[6];
    const float* bk = (const float*)d_in[7];
    const float* Wv = (const float*)d_in[8];
    const float* bv = (const float*)d_in[9];
    const float* Ww = (const float*)d_in[10];
    const float* bw = (const float*)d_in[11];
    const float* Wa = (const float*)d_in[12];
    const float* ba = (const float*)d_in[13];
    const float* wb = (const float*)d_in[14];
    const float* bb = (const float*)d_in[15];
    float* out = (float*)d_out;

    float *kbuf, *x, *qk2, *v2T, *s2, *wqkT, *wvT, *bqk, *efea, *qe;
    cudaGetSymbolAddress((void**)&kbuf, g_kbuf);
    cudaGetSymbolAddress((void**)&x,    g_x);
    cudaGetSymbolAddress((void**)&qk2,  g_qk2);
    cudaGetSymbolAddress((void**)&v2T,  g_v2T);
    cudaGetSymbolAddress((void**)&s2,   g_s2);
    cudaGetSymbolAddress((void**)&wqkT, g_wqkT);
    cudaGetSymbolAddress((void**)&wvT,  g_wvT);
    cudaGetSymbolAddress((void**)&bqk,  g_bqk);
    cudaGetSymbolAddress((void**)&efea, g_efea);
    cudaGetSymbolAddress((void**)&qe,   g_qe);

    cudaFuncSetAttribute(mm_gemm_kernel, cudaFuncAttributeMaxDynamicSharedMemorySize, GE_SMEM_BYTES);

    const float inv_sqrt_d = 0.08838834764831845f;

    // all weight prep in one launch
    prep_kernel<<<769, dim3(32, 8)>>>(Wq, Wk, Wv, bq, bk);

    // entity features: gather + feas/c1 (writes g_efea), then qe via GEMM
    feasC1_kernel<<<CB * CT, 256>>>(xs, spans, Ww, bw, Wa);
    mm_gemm_kernel<<<dim3(1, 2, 1), 256, GE_SMEM_BYTES>>>(
        efea, wqkT, bq, qe, CB*CT*CE, CD, CH, 1.0f, CH, CH, CD, 1, 0, 0, 0);

    // k projection: [65536,768] @ WkT^T -> [65536,128]
    mm_gemm_kernel<<<dim3(1, 512, 1), 256, GE_SMEM_BYTES>>>(
        neigh, wqkT + CD * CH, bk, kbuf, CB*CT*CN*CL, CD, CH, 1.0f, CH, CH, CD, 1, 0, 0, 0);

    // per-neighbor SDPA + messages + scores
    stageB_kernel<<<CB * CT * CN, 256>>>(neigh, dists, Ww, bw, Wa, ba, wb, bb);

    // x = xs + scattered deltas (fused, overlap-safe)
    copy_scatter_kernel<<<(CB * CS * CH / 4 + 255) / 256, 256>>>(xs, spans);

    // fused q2|k2 projection: [8192,768] @ wqkT^T -> [8192,256]
    mm_gemm_kernel<<<dim3(2, 64, 1), 256, GE_SMEM_BYTES>>>(
        x, wqkT, bqk, qk2, CB * CS, 2 * CD, CH, 1.0f, CH, CH, 2 * CD, 1, 0, 0, 0);

    // v2T = wvT @ x^T per batch: [768,512], row-bias bv
    mm_gemm_kernel<<<dim3(4, 6, CB), 256, GE_SMEM_BYTES>>>(
        wvT, x, bv, v2T, CH, CS, CH, 1.0f, CH, CH, CS, 2,
        0, (long long)CS * CH, (long long)CH * CS);

    // s2 = q2 @ k2^T * inv_sqrt_d (batched; q2/k2 interleaved in qk2)
    mm_gemm_kernel<<<dim3(4, 4, CB), 256, GE_SMEM_BYTES>>>(
        qk2, qk2 + CD, nullptr, s2, CS, CS, CD, inv_sqrt_d, 2 * CD, 2 * CD, CS, 0,
        (long long)CS * 2 * CD, (long long)CS * 2 * CD, (long long)CS * CS);

    softmax_kernel<<<CB * CS, 256>>>();

    // out = softmax(s2) @ v2  (B operand = v2T [768,512], batched)
    mm_gemm_kernel<<<dim3(6, 4, CB), 256, GE_SMEM_BYTES>>>(
        s2, v2T, nullptr, out, CS, CH, CS, 1.0f, CS, CS, CH, 0,
        (long long)CS * CS, (long long)CH * CS, (long long)CS * CH);
}

// round 15
// speedup vs baseline: 1.3788x; 1.0380x over previous
#include <cuda_runtime.h>
#include <math.h>
#include <stdint.h>

// Problem constants
#define CB 16
#define CS 512
#define CH 768
#define CT 2
#define CN 32
#define CL 64
#define CE 8
#define CD 128
#define CA 128

// ---------------- scratch (device globals; no allocation allowed) ----------------
__device__ float g_kbuf[CB*CT*CN*CL*CD];       // neighbor k projections
__device__ float g_msgs[CB*CT*CN*CE*CH];       // per-neighbor messages
__device__ float g_score[CB*CT*CN];
__device__ float g_c1[CB*CT];
__device__ float g_qe[CB*CT*CE*CD];
__device__ float g_efea[CB*CT*CE*CH];          // gathered entity span features [256,768]
__device__ float g_x[CB*CS*CH];
__device__ float g_qk2[CB*CS*2*CD];            // fused q2|k2 [B*S, 256]
__device__ float g_v2T[CB*CH*CS];              // v2 transposed per batch [B][768][512]
__device__ float g_s2[CB*CS*CS];
__device__ float g_wqkT[2*CD*CH];              // [WqT; WkT] [256,768]
__device__ float g_wvT[CH*CH];
__device__ float g_bqk[2*CD];

// ================= tf32 mma.sync GEMM (CTA 128x128, warp 32x64, single-sync pipeline) =====
// A [M,K] rows lda, B [N,K] rows ldb, C [M,N] rows ldc. M,N mult 128, K mult 32.
// bias_mode: 0 none, 1 per-col, 2 per-row. Batched via blockIdx.z (strides sA,sB,sC).
// __launch_bounds__(256, 2): cap regs at 128 so 2 CTAs co-reside per SM.
// Fragment SMEM layout with ks-XOR swizzle: slot s stored at s^ks, read back at lane^ks.
// Kills the 4-way STS bank conflicts (B now conflict-free, A 2-way).

#define GE_SMEM_BYTES 65536

__device__ __forceinline__ void mma_tf32(float c[4], const uint32_t a[4], const uint32_t b[2]) {
    asm volatile(
        "mma.sync.aligned.m16n8k8.row.col.f32.tf32.tf32.f32 "
        "{%0,%1,%2,%3}, {%4,%5,%6,%7}, {%8,%9}, {%0,%1,%2,%3};"
        : "+f"(c[0]), "+f"(c[1]), "+f"(c[2]), "+f"(c[3])
        : "r"(a[0]), "r"(a[1]), "r"(a[2]), "r"(a[3]), "r"(b[0]), "r"(b[1]));
}

__device__ __forceinline__ void tile_ldg(const float* __restrict__ p, int lda, int tid, float4 r[4]) {
    #pragma unroll
    for (int j = 0; j < 4; j++) {
        int f = j * 256 + tid;
        int row = f >> 3, c4 = f & 7;
        float4 v = *reinterpret_cast<const float4*>(p + (long long)row * lda + c4 * 4);
        asm volatile("cvt.rna.tf32.f32 %0, %0;" : "+r"(*(uint32_t*)&v.x));
        asm volatile("cvt.rna.tf32.f32 %0, %0;" : "+r"(*(uint32_t*)&v.y));
        asm volatile("cvt.rna.tf32.f32 %0, %0;" : "+r"(*(uint32_t*)&v.z));
        asm volatile("cvt.rna.tf32.f32 %0, %0;" : "+r"(*(uint32_t*)&v.w));
        r[j] = v;
    }
}

// A fragment store: slot (g*4+t) ^ ks at [ks][mt][slot][jf]
__device__ __forceinline__ void sts_fragA(float* sm, int tid, const float4 r[4]) {
    #pragma unroll
    for (int j = 0; j < 4; j++) {
        int f = j * 256 + tid;
        int row = f >> 3, c4 = f & 7;
        int ks = c4 >> 1;
        int jfrag = ((row >> 3) & 1) + ((c4 & 1) << 1);
        int mt = row >> 4, g = row & 7;
        float* base = sm + (((ks * 8 + mt) * 32) << 2) + jfrag;
        const float* v = reinterpret_cast<const float*>(&r[j]);
        #pragma unroll
        for (int t = 0; t < 4; t++) base[((g * 4 + t) ^ ks) << 2] = v[t];
    }
}

// B fragment store: slot (g*4+t) ^ ks at [ks][nt][slot][jf]
__device__ __forceinline__ void sts_fragB(float* sm, int tid, const float4 r[4]) {
    #pragma unroll
    for (int j = 0; j < 4; j++) {
        int f = j * 256 + tid;
        int row = f >> 3, c4 = f & 7;
        int ks = c4 >> 1;
        int jfrag = c4 & 1;
        int nt = row >> 3, g = row & 7;
        float* base = sm + (((ks * 16 + nt) * 32) << 1) + jfrag;
        const float* v = reinterpret_cast<const float*>(&r[j]);
        #pragma unroll
        for (int t = 0; t < 4; t++) base[((g * 4 + t) ^ ks) << 1] = v[t];
    }
}

__global__ void __launch_bounds__(256, 2)
mm_gemm_kernel(const float* __restrict__ A, const float* __restrict__ B,
               const float* __restrict__ bias, float* __restrict__ C,
               int M, int N, int K, float alpha,
               int lda, int ldb, int ldc, int bias_mode,
               long long sA, long long sB, long long sC)
{
    extern __shared__ float smem[];
    float* smA[2] = { smem,          smem + 8192 };
    float* smB[2] = { smem + 4096,   smem + 12288 };

    int tid = threadIdx.x;
    int wid = tid >> 5, lane = tid & 31;
    int warpM = wid & 3;
    int warpN = wid >> 2;

    const float* Ab = A + (long long)blockIdx.z * sA + (long long)(blockIdx.y * 128) * lda;
    const float* Bb = B + (long long)blockIdx.z * sB + (long long)(blockIdx.x * 128) * ldb;

    float acc[2][8][4];
    #pragma unroll
    for (int i = 0; i < 2; i++)
        #pragma unroll
        for (int j = 0; j < 8; j++)
            #pragma unroll
            for (int c = 0; c < 4; c++) acc[i][j][c] = 0.f;

    int nch = K >> 5;
    float4 ra[4], rb[4];
    tile_ldg(Ab, lda, tid, ra);
    tile_ldg(Bb, ldb, tid, rb);
    sts_fragA(smA[0], tid, ra);
    sts_fragB(smB[0], tid, rb);

    // single-sync pipeline: sync -> LDG(i+1) -> MMA(i) -> STS(i+1)
    for (int i = 0; i < nch; i++) {
        int buf = i & 1;
        __syncthreads();
        bool more = (i + 1 < nch);
        if (more) {
            tile_ldg(Ab + (i + 1) * 32, lda, tid, ra);
            tile_ldg(Bb + (i + 1) * 32, ldb, tid, rb);
        }
        #pragma unroll
        for (int ks = 0; ks < 4; ks++) {
            int sl = lane ^ ks;
            const float* fA = smA[buf] + (ks * 8 + warpM * 2) * 128 + sl * 4;
            const float* fB = smB[buf] + (ks * 16 + warpN * 8) * 64 + sl * 2;
            uint32_t afr[2][4];
            #pragma unroll
            for (int mt = 0; mt < 2; mt++) {
                float4 v = *reinterpret_cast<const float4*>(fA + mt * 128);
                afr[mt][0] = __float_as_uint(v.x); afr[mt][1] = __float_as_uint(v.y);
                afr[mt][2] = __float_as_uint(v.z); afr[mt][3] = __float_as_uint(v.w);
            }
            #pragma unroll
            for (int nt = 0; nt < 8; nt++) {
                float2 v = *reinterpret_cast<const float2*>(fB + nt * 64);
                uint32_t bfr[2] = { __float_as_uint(v.x), __float_as_uint(v.y) };
                mma_tf32(acc[0][nt], afr[0], bfr);
                mma_tf32(acc[1][nt], afr[1], bfr);
            }
        }
        if (more) {
            sts_fragA(smA[buf ^ 1], tid, ra);
            sts_fragB(smB[buf ^ 1], tid, rb);
        }
    }

    int g = lane >> 2, t = lane & 3;
    long long crow0 = (long long)(blockIdx.y * 128 + warpM * 32 + g);
    int col0 = blockIdx.x * 128 + warpN * 64 + t * 2;
    float* Cb = C + (long long)blockIdx.z * sC;
    #pragma unroll
    for (int mt = 0; mt < 2; mt++) {
        long long r0 = crow0 + mt * 16;
        float br0 = 0.f, br1 = 0.f;
        if (bias_mode == 2) { br0 = bias[r0]; br1 = bias[r0 + 8]; }
        #pragma unroll
        for (int nt = 0; nt < 8; nt++) {
            int cc = col0 + nt * 8;
            float bcx = 0.f, bcy = 0.f;
            if (bias_mode == 1) { bcx = bias[cc]; bcy = bias[cc + 1]; }
            float2 v0 = { acc[mt][nt][0] * alpha + bcx + br0, acc[mt][nt][1] * alpha + bcy + br0 };
            float2 v1 = { acc[mt][nt][2] * alpha + bcx + br1, acc[mt][nt][3] * alpha + bcy + br1 };
            *reinterpret_cast<float2*>(Cb + r0 * ldc + cc) = v0;
            *reinterpret_cast<float2*>(Cb + (r0 + 8) * ldc + cc) = v1;
        }
    }
}

// ---------------- prep: all weight transposes + bias pack in ONE launch ----------------
__global__ void prep_kernel(const float* __restrict__ Wq, const float* __restrict__ Wk,
                            const float* __restrict__ Wv,
                            const float* __restrict__ bq, const float* __restrict__ bk) {
    int bid = blockIdx.x;
    int x = threadIdx.x, y = threadIdx.y;      // 32 x 8
    if (bid == 768) {
        int i = y * 32 + x;
        g_bqk[i] = (i < CD) ? bq[i] : bk[i - CD];
        return;
    }
    const float* src; float* dst; int R, C, tile;
    if (bid < 96)       { src = Wq; dst = g_wqkT;            R = CH; C = CD; tile = bid; }
    else if (bid < 192) { src = Wk; dst = g_wqkT + CD * CH;  R = CH; C = CD; tile = bid - 96; }
    else                { src = Wv; dst = g_wvT;             R = CH; C = CH; tile = bid - 192; }
    int tcols = C >> 5;
    int c0 = (tile % tcols) * 32, r0 = (tile / tcols) * 32;
    __shared__ float t[32][33];
    #pragma unroll
    for (int j = 0; j < 32; j += 8)
        t[y + j][x] = src[(long long)(r0 + y + j) * C + c0 + x];
    __syncthreads();
    #pragma unroll
    for (int j = 0; j < 32; j += 8)
        dst[(long long)(c0 + y + j) * R + r0 + x] = t[x][y + j];
}

// ---------------- feasC1 (+ efea gather): per-bt block ----------------
__global__ void feasC1_kernel(const float* __restrict__ xs, const int* __restrict__ spans,
                              const float* __restrict__ Ww, const float* __restrict__ bw,
                              const float* __restrict__ Wa) {
    int bt = blockIdx.x;           // 32 blocks, 256 threads
    int b = bt >> 1;
    int tid = threadIdx.x;
    int span = spans[bt];
    __shared__ float s_e[CE * CH];     // 24KB
    __shared__ float s_f[CH];
    __shared__ float s_r[4];
    float4* ep = reinterpret_cast<float4*>(&g_efea[bt * CE * CH]);
    #pragma unroll
    for (int j = 0; j < 6; j++) {
        int f = j * 256 + tid;             // over 1536 float4
        int e = f / 192, c4 = f % 192;
        float4 v = *reinterpret_cast<const float4*>(
            &xs[((long long)b * CS + span + e) * CH + c4 * 4]);
        reinterpret_cast<float4*>(s_e)[f] = v;
        ep[f] = v;
    }
    __syncthreads();
    for (int h = tid; h < CH; h += 256) {
        float a = 0.f;
        #pragma unroll
        for (int e = 0; e < CE; e++) a += s_e[e * CH + h];
        s_f[h] = a * (1.0f / CE);
    }
    __syncthreads();
    if (tid < 128) {
        float acc = bw[tid];
        for (int h = 0; h < CH; h++) acc += s_f[h] * Ww[h * CA + tid];
        float part = acc * Wa[tid];
        #pragma unroll
        for (int off = 16; off; off >>= 1) part += __shfl_xor_sync(0xffffffffu, part, off);
        if ((tid & 31) == 0) s_r[tid >> 5] = part;
    }
    __syncthreads();
    if (tid == 0) g_c1[bt] = s_r[0] + s_r[1] + s_r[2] + s_r[3];
}

// ---------------- stage B (vectorized): per-neighbor SDPA + messages + score ----------------
#define KCP (CD + 4)   // 132-word pitch
__global__ void stageB_kernel(const float* __restrict__ neigh, const float* __restrict__ dists,
                              const float* __restrict__ Ww, const float* __restrict__ bw,
                              const float* __restrict__ Wa, const float* __restrict__ ba,
                              const float* __restrict__ wb, const float* __restrict__ bb) {
    int bid = blockIdx.x;                 // B*T*N = 1024 blocks, 256 threads
    int bt = bid / CN, n = bid % CN;
    int tid = threadIdx.x;
    const float inv_sqrt_d = 0.08838834764831845f;

    __shared__ float s_q[CE * CD];        // 4KB; aliased as red4 after logits
    __shared__ float s_kc[CL * KCP];      // 33KB
    __shared__ float s_attn[CE * CL];     // 2KB
    __shared__ float s_pooled[CH];        // 3KB
    __shared__ float s_red[256];          // 1KB

    reinterpret_cast<float4*>(s_q)[tid] =
        reinterpret_cast<const float4*>(&g_qe[bt * CE * CD])[tid];
    {
        const float4* kp = reinterpret_cast<const float4*>(&g_kbuf[(long long)bid * CL * CD]);
        #pragma unroll
        for (int j = 0; j < 8; j++) {
            int f = j * 256 + tid;
            int l = f >> 5, c4 = f & 31;
            *reinterpret_cast<float4*>(&s_kc[l * KCP + c4 * 4]) = kp[f];
        }
    }
    __syncthreads();

    #pragma unroll
    for (int r = 0; r < 2; r++) {
        int o = r * 256 + tid;
        int e = o >> 6, l = o & 63;
        const float4* q4 = reinterpret_cast<const float4*>(&s_q[e * CD]);
        const float4* k4 = reinterpret_cast<const float4*>(&s_kc[l * KCP]);
        float acc = 0.f;
        #pragma unroll 8
        for (int d = 0; d < 32; d++) {
            float4 a = q4[d], b = k4[d];
            acc += a.x * b.x + a.y * b.y + a.z * b.z + a.w * b.w;
        }
        s_attn[o] = acc * inv_sqrt_d;
    }
    __syncthreads();

    {
        int w = tid >> 5, lane = tid & 31;
        if (w < CE) {
            float v1 = s_attn[w * CL + lane], v2 = s_attn[w * CL + lane + 32];
            float m = fmaxf(v1, v2);
            #pragma unroll
            for (int off = 16; off; off >>= 1) m = fmaxf(m, __shfl_xor_sync(0xffffffffu, m, off));
            float e1 = __expf(v1 - m), e2 = __expf(v2 - m);
            float s = e1 + e2;
            #pragma unroll
            for (int off = 16; off; off >>= 1) s += __shfl_xor_sync(0xffffffffu, s, off);
            float inv = 1.0f / s;
            s_attn[w * CL + lane] = e1 * inv;
            s_attn[w * CL + lane + 32] = e2 * inv;
        }
    }
    __syncthreads();

    float* s_red4 = s_q;   // alias
    const long long nb = ((long long)bid) * CL * CH;
    const long long mb = ((long long)bid) * CE * CH;
    int e = tid >> 5, jg = tid & 31;
    for (int hc = 0; hc < CH; hc += 128) {
        #pragma unroll
        for (int j = 0; j < 8; j++) {
            int f = j * 256 + tid;
            int l = f >> 5, c4 = f & 31;
            *reinterpret_cast<float4*>(&s_kc[l * KCP + c4 * 4]) =
                *reinterpret_cast<const float4*>(&neigh[nb + (long long)l * CH + hc + c4 * 4]);
        }
        __syncthreads();
        float4 acc = {0.f, 0.f, 0.f, 0.f};
        const float* at = &s_attn[e * CL];
        #pragma unroll 16
        for (int l = 0; l < CL; l++) {
            float a = at[l];
            float4 k = *reinterpret_cast<const float4*>(&s_kc[l * KCP + jg * 4]);
            acc.x += a * k.x; acc.y += a * k.y; acc.z += a * k.z; acc.w += a * k.w;
        }
        *reinterpret_cast<float4*>(&g_msgs[mb + (long long)e * CH + hc + jg * 4]) = acc;
        *reinterpret_cast<float4*>(&s_red4[tid * 4]) = acc;
        __syncthreads();
        if (tid < 128) {
            int jg2 = tid >> 2, comp = tid & 3;
            float s = 0.f;
            #pragma unroll
            for (int e2 = 0; e2 < CE; e2++) s += s_red4[(e2 * 32 + jg2) * 4 + comp];
            s_pooled[hc + tid] = s * (1.0f / CE);
        }
        __syncthreads();
    }

    float part = 0.f;
    if (tid < CA) {
        float acc = bw[tid];
        for (int h = 0; h < CH; h++) acc += s_pooled[h] * Ww[h * CA + tid];
        part = acc * Wa[CA + tid];
    }
    s_red[tid] = part;
    __syncthreads();
    for (int s = 128; s > 0; s >>= 1) {
        if (tid < s) s_red[tid] += s_red[tid + s];
        __syncthreads();
    }
    if (tid == 0) {
        float v = g_c1[bt] + s_red[0] + ba[0];
        v = (v > 0.f) ? v : 0.01f * v;
        v += dists[bt * CN + n] * wb[0] + bb[0];
        g_score[bt * CN + n] = 1.0f / (1.0f + __expf(-v));
    }
}

// ---------------- fused copy + scatter: x = xs, spans get score-weighted messages ----------------
__global__ void copy_scatter_kernel(const float* __restrict__ xs, const int* __restrict__ spans) {
    int i4 = blockIdx.x * blockDim.x + threadIdx.x;      // over B*S*H/4 = 1572864
    const int total4 = CB * CS * CH / 4;
    if (i4 >= total4) return;
    int f = i4 * 4;
    int b = f / (CS * CH);
    int r = f % (CS * CH);
    int s = r / CH, h = r % CH;
    float4 v = reinterpret_cast<const float4*>(xs)[i4];
    #pragma unroll
    for (int t = 0; t < 2; t++) {
        int bt = b * CT + t;
        int e = s - spans[bt];
        if (e >= 0 && e < CE) {
            const float* sc = &g_score[bt * CN];
            const float* ms = &g_msgs[(((long long)bt * CN) * CE + e) * CH + h];
            float4 d = {0.f, 0.f, 0.f, 0.f};
            #pragma unroll 8
            for (int n = 0; n < CN; n++) {
                float a = sc[n];
                float4 m = *reinterpret_cast<const float4*>(ms + (long long)n * CE * CH);
                d.x += a * m.x; d.y += a * m.y; d.z += a * m.z; d.w += a * m.w;
            }
            v.x += d.x; v.y += d.y; v.z += d.z; v.w += d.w;
        }
    }
    reinterpret_cast<float4*>(g_x)[i4] = v;
}

// ---------------- row softmax for s2 ----------------
__global__ void softmax_kernel() {
    int row = blockIdx.x;
    int tid = threadIdx.x;
    float* p = &g_s2[(long long)row * CS];
    __shared__ float s_red[256];
    float v1 = p[tid], v2 = p[tid + 256];
    float m = fmaxf(v1, v2);
    s_red[tid] = m;
    __syncthreads();
    for (int s = 128; s > 0; s >>= 1) { if (tid < s) s_red[tid] = fmaxf(s_red[tid], s_red[tid + s]); __syncthreads(); }
    m = s_red[0];
    __syncthreads();
    float e1 = __expf(v1 - m), e2 = __expf(v2 - m);
    s_red[tid] = e1 + e2;
    __syncthreads();
    for (int s = 128; s > 0; s >>= 1) { if (tid < s) s_red[tid] += s_red[tid + s]; __syncthreads(); }
    float inv = 1.0f / s_red[0];
    p[tid] = e1 * inv;
    p[tid + 256] = e2 * inv;
}

// ---------------- host ----------------
extern "C" void kernel_launch(void* const* d_in, const int* in_sizes, int n_in,
                              void* d_out, int out_size) {
    const float* xs    = (const float*)d_in[0];
    const float* neigh = (const float*)d_in[1];
    const float* dists = (const float*)d_in[2];
    const int*   spans = (const int*)d_in[3];
    const float* Wq = (const float*)d_in[4];
    const float* bq = (const float*)d_in[5];
    const float* Wk = (const float*)d_in[6];
    const float* bk = (const float*)d_in[7];
    const float* Wv = (const float*)d_in[8];
    const float* bv = (const float*)d_in[9];
    const float* Ww = (const float*)d_in[10];
    const float* bw = (const float*)d_in[11];
    const float* Wa = (const float*)d_in[12];
    const float* ba = (const float*)d_in[13];
    const float* wb = (const float*)d_in[14];
    const float* bb = (const float*)d_in[15];
    float* out = (float*)d_out;

    float *kbuf, *x, *qk2, *v2T, *s2, *wqkT, *wvT, *bqk, *efea, *qe;
    cudaGetSymbolAddress((void**)&kbuf, g_kbuf);
    cudaGetSymbolAddress((void**)&x,    g_x);
    cudaGetSymbolAddress((void**)&qk2,  g_qk2);
    cudaGetSymbolAddress((void**)&v2T,  g_v2T);
    cudaGetSymbolAddress((void**)&s2,   g_s2);
    cudaGetSymbolAddress((void**)&wqkT, g_wqkT);
    cudaGetSymbolAddress((void**)&wvT,  g_wvT);
    cudaGetSymbolAddress((void**)&bqk,  g_bqk);
    cudaGetSymbolAddress((void**)&efea, g_efea);
    cudaGetSymbolAddress((void**)&qe,   g_qe);

    cudaFuncSetAttribute(mm_gemm_kernel, cudaFuncAttributeMaxDynamicSharedMemorySize, GE_SMEM_BYTES);

    const float inv_sqrt_d = 0.08838834764831845f;

    // all weight prep in one launch
    prep_kernel<<<769, dim3(32, 8)>>>(Wq, Wk, Wv, bq, bk);

    // entity features: gather + feas/c1 (writes g_efea), then qe via GEMM
    feasC1_kernel<<<CB * CT, 256>>>(xs, spans, Ww, bw, Wa);
    mm_gemm_kernel<<<dim3(1, 2, 1), 256, GE_SMEM_BYTES>>>(
        efea, wqkT, bq, qe, CB*CT*CE, CD, CH, 1.0f, CH, CH, CD, 1, 0, 0, 0);

    // k projection: [65536,768] @ WkT^T -> [65536,128]
    mm_gemm_kernel<<<dim3(1, 512, 1), 256, GE_SMEM_BYTES>>>(
        neigh, wqkT + CD * CH, bk, kbuf, CB*CT*CN*CL, CD, CH, 1.0f, CH, CH, CD, 1, 0, 0, 0);

    // per-neighbor SDPA + messages + scores
    stageB_kernel<<<CB * CT * CN, 256>>>(neigh, dists, Ww, bw, Wa, ba, wb, bb);

    // x = xs + scattered deltas (fused, overlap-safe)
    copy_scatter_kernel<<<(CB * CS * CH / 4 + 255) / 256, 256>>>(xs, spans);

    // fused q2|k2 projection: [8192,768] @ wqkT^T -> [8192,256]
    mm_gemm_kernel<<<dim3(2, 64, 1), 256, GE_SMEM_BYTES>>>(
        x, wqkT, bqk, qk2, CB * CS, 2 * CD, CH, 1.0f, CH, CH, 2 * CD, 1, 0, 0, 0);

    // v2T = wvT @ x^T per batch: [768,512], row-bias bv
    mm_gemm_kernel<<<dim3(4, 6, CB), 256, GE_SMEM_BYTES>>>(
        wvT, x, bv, v2T, CH, CS, CH, 1.0f, CH, CH, CS, 2,
        0, (long long)CS * CH, (long long)CH * CS);

    // s2 = q2 @ k2^T * inv_sqrt_d (batched; q2/k2 interleaved in qk2)
    mm_gemm_kernel<<<dim3(4, 4, CB), 256, GE_SMEM_BYTES>>>(
        qk2, qk2 + CD, nullptr, s2, CS, CS, CD, inv_sqrt_d, 2 * CD, 2 * CD, CS, 0,
        (long long)CS * 2 * CD, (long long)CS * 2 * CD, (long long)CS * CS);

    softmax_kernel<<<CB * CS, 256>>>();

    // out = softmax(s2) @ v2  (B operand = v2T [768,512], batched)
    mm_gemm_kernel<<<dim3(6, 4, CB), 256, GE_SMEM_BYTES>>>(
        s2, v2T, nullptr, out, CS, CH, CS, 1.0f, CS, CS, CH, 0,
        (long long)CS * CS, (long long)CH * CS, (long long)CS * CH);
}

// round 16
// speedup vs baseline: 1.6074x; 1.1658x over previous
#include <cuda_runtime.h>
#include <math.h>
#include <stdint.h>

// Problem constants
#define CB 16
#define CS 512
#define CH 768
#define CT 2
#define CN 32
#define CL 64
#define CE 8
#define CD 128
#define CA 128

// ---------------- scratch (device globals; no allocation allowed) ----------------
__device__ float g_kbuf[CB*CT*CN*CL*CD];       // neighbor k projections
__device__ float g_msgs[CB*CT*CN*CE*CH];       // per-neighbor messages
__device__ float g_score[CB*CT*CN];
__device__ float g_c1[CB*CT];
__device__ float g_qe[CB*CT*CE*CD];
__device__ float g_efea[CB*CT*CE*CH];          // gathered entity span features [256,768]
__device__ float g_x[CB*CS*CH];
__device__ float g_qk2[CB*CS*2*CD];            // fused q2|k2 [B*S, 256]
__device__ float g_v2T[CB*CH*CS];              // v2 transposed per batch [B][768][512]
__device__ float g_s2[CB*CS*CS];
__device__ float g_wqkT[2*CD*CH];              // [WqT; WkT] [256,768]
__device__ float g_wvT[CH*CH];
__device__ float g_bqk[2*CD];

// ================= tf32 mma.sync GEMM (CTA 128x128, warp 32x64) =====
// Triple-buffered SMEM, prefetch distance 2: sync -> STS(i+1) -> LDG(i+2) -> MMA(i).
// A [M,K] rows lda, B [N,K] rows ldb, C [M,N] rows ldc. M,N mult 128, K mult 32.
// bias_mode: 0 none, 1 per-col, 2 per-row. Batched via blockIdx.z (strides sA,sB,sC).
// __launch_bounds__(256, 2): regs capped at 128; 2 CTAs/SM (192KB smem total).
// Fragment SMEM with ks-XOR swizzle (slot s stored at s^ks, read at lane^ks).

#define GE_SMEM_BYTES 98304   // 3 buffers x (A 16KB + B 16KB)

__device__ __forceinline__ void mma_tf32(float c[4], const uint32_t a[4], const uint32_t b[2]) {
    asm volatile(
        "mma.sync.aligned.m16n8k8.row.col.f32.tf32.tf32.f32 "
        "{%0,%1,%2,%3}, {%4,%5,%6,%7}, {%8,%9}, {%0,%1,%2,%3};"
        : "+f"(c[0]), "+f"(c[1]), "+f"(c[2]), "+f"(c[3])
        : "r"(a[0]), "r"(a[1]), "r"(a[2]), "r"(a[3]), "r"(b[0]), "r"(b[1]));
}

__device__ __forceinline__ void tile_ldg(const float* __restrict__ p, int lda, int tid, float4 r[4]) {
    #pragma unroll
    for (int j = 0; j < 4; j++) {
        int f = j * 256 + tid;
        int row = f >> 3, c4 = f & 7;
        float4 v = *reinterpret_cast<const float4*>(p + (long long)row * lda + c4 * 4);
        asm volatile("cvt.rna.tf32.f32 %0, %0;" : "+r"(*(uint32_t*)&v.x));
        asm volatile("cvt.rna.tf32.f32 %0, %0;" : "+r"(*(uint32_t*)&v.y));
        asm volatile("cvt.rna.tf32.f32 %0, %0;" : "+r"(*(uint32_t*)&v.z));
        asm volatile("cvt.rna.tf32.f32 %0, %0;" : "+r"(*(uint32_t*)&v.w));
        r[j] = v;
    }
}

// A fragment store: slot (g*4+t) ^ ks at [ks][mt][slot][jf]
__device__ __forceinline__ void sts_fragA(float* sm, int tid, const float4 r[4]) {
    #pragma unroll
    for (int j = 0; j < 4; j++) {
        int f = j * 256 + tid;
        int row = f >> 3, c4 = f & 7;
        int ks = c4 >> 1;
        int jfrag = ((row >> 3) & 1) + ((c4 & 1) << 1);
        int mt = row >> 4, g = row & 7;
        float* base = sm + (((ks * 8 + mt) * 32) << 2) + jfrag;
        const float* v = reinterpret_cast<const float*>(&r[j]);
        #pragma unroll
        for (int t = 0; t < 4; t++) base[((g * 4 + t) ^ ks) << 2] = v[t];
    }
}

// B fragment store: slot (g*4+t) ^ ks at [ks][nt][slot][jf]
__device__ __forceinline__ void sts_fragB(float* sm, int tid, const float4 r[4]) {
    #pragma unroll
    for (int j = 0; j < 4; j++) {
        int f = j * 256 + tid;
        int row = f >> 3, c4 = f & 7;
        int ks = c4 >> 1;
        int jfrag = c4 & 1;
        int nt = row >> 3, g = row & 7;
        float* base = sm + (((ks * 16 + nt) * 32) << 1) + jfrag;
        const float* v = reinterpret_cast<const float*>(&r[j]);
        #pragma unroll
        for (int t = 0; t < 4; t++) base[((g * 4 + t) ^ ks) << 1] = v[t];
    }
}

__global__ void __launch_bounds__(256, 2)
mm_gemm_kernel(const float* __restrict__ A, const float* __restrict__ B,
               const float* __restrict__ bias, float* __restrict__ C,
               int M, int N, int K, float alpha,
               int lda, int ldb, int ldc, int bias_mode,
               long long sA, long long sB, long long sC)
{
    extern __shared__ float smem[];
    // 3 buffers: buffer b at smem + b*8192 (A first 4096, B next 4096)
    int tid = threadIdx.x;
    int wid = tid >> 5, lane = tid & 31;
    int warpM = wid & 3;
    int warpN = wid >> 2;

    const float* Ab = A + (long long)blockIdx.z * sA + (long long)(blockIdx.y * 128) * lda;
    const float* Bb = B + (long long)blockIdx.z * sB + (long long)(blockIdx.x * 128) * ldb;

    float acc[2][8][4];
    #pragma unroll
    for (int i = 0; i < 2; i++)
        #pragma unroll
        for (int j = 0; j < 8; j++)
            #pragma unroll
            for (int c = 0; c < 4; c++) acc[i][j][c] = 0.f;

    int nch = K >> 5;
    float4 ra[4], rb[4];
    // prologue: chunk0 -> buf0 (SMEM), chunk1 -> regs
    tile_ldg(Ab, lda, tid, ra);
    tile_ldg(Bb, ldb, tid, rb);
    sts_fragA(smem, tid, ra);
    sts_fragB(smem + 4096, tid, rb);
    if (nch > 1) {
        tile_ldg(Ab + 32, lda, tid, ra);
        tile_ldg(Bb + 32, ldb, tid, rb);
    }

    int buf = 0, nbuf = 1;
    for (int i = 0; i < nch; i++) {
        __syncthreads();
        // store prefetched chunk i+1 (regs loaded a full iteration ago)
        if (i + 1 < nch) {
            sts_fragA(smem + nbuf * 8192, tid, ra);
            sts_fragB(smem + nbuf * 8192 + 4096, tid, rb);
        }
        // prefetch chunk i+2 into regs
        if (i + 2 < nch) {
            tile_ldg(Ab + (i + 2) * 32, lda, tid, ra);
            tile_ldg(Bb + (i + 2) * 32, ldb, tid, rb);
        }
        // MMA on chunk i
        const float* bufA = smem + buf * 8192;
        const float* bufB = smem + buf * 8192 + 4096;
        #pragma unroll
        for (int ks = 0; ks < 4; ks++) {
            int sl = lane ^ ks;
            const float* fA = bufA + (ks * 8 + warpM * 2) * 128 + sl * 4;
            const float* fB = bufB + (ks * 16 + warpN * 8) * 64 + sl * 2;
            uint32_t afr[2][4];
            #pragma unroll
            for (int mt = 0; mt < 2; mt++) {
                float4 v = *reinterpret_cast<const float4*>(fA + mt * 128);
                afr[mt][0] = __float_as_uint(v.x); afr[mt][1] = __float_as_uint(v.y);
                afr[mt][2] = __float_as_uint(v.z); afr[mt][3] = __float_as_uint(v.w);
            }
            #pragma unroll
            for (int nt = 0; nt < 8; nt++) {
                float2 v = *reinterpret_cast<const float2*>(fB + nt * 64);
                uint32_t bfr[2] = { __float_as_uint(v.x), __float_as_uint(v.y) };
                mma_tf32(acc[0][nt], afr[0], bfr);
                mma_tf32(acc[1][nt], afr[1], bfr);
            }
        }
        buf = nbuf;
        nbuf = (nbuf + 1 == 3) ? 0 : nbuf + 1;
    }

    int g = lane >> 2, t = lane & 3;
    long long crow0 = (long long)(blockIdx.y * 128 + warpM * 32 + g);
    int col0 = blockIdx.x * 128 + warpN * 64 + t * 2;
    float* Cb = C + (long long)blockIdx.z * sC;
    #pragma unroll
    for (int mt = 0; mt < 2; mt++) {
        long long r0 = crow0 + mt * 16;
        float br0 = 0.f, br1 = 0.f;
        if (bias_mode == 2) { br0 = bias[r0]; br1 = bias[r0 + 8]; }
        #pragma unroll
        for (int nt = 0; nt < 8; nt++) {
            int cc = col0 + nt * 8;
            float bcx = 0.f, bcy = 0.f;
            if (bias_mode == 1) { bcx = bias[cc]; bcy = bias[cc + 1]; }
            float2 v0 = { acc[mt][nt][0] * alpha + bcx + br0, acc[mt][nt][1] * alpha + bcy + br0 };
            float2 v1 = { acc[mt][nt][2] * alpha + bcx + br1, acc[mt][nt][3] * alpha + bcy + br1 };
            *reinterpret_cast<float2*>(Cb + r0 * ldc + cc) = v0;
            *reinterpret_cast<float2*>(Cb + (r0 + 8) * ldc + cc) = v1;
        }
    }
}

// ---------------- prep: all weight transposes + bias pack in ONE launch ----------------
__global__ void prep_kernel(const float* __restrict__ Wq, const float* __restrict__ Wk,
                            const float* __restrict__ Wv,
                            const float* __restrict__ bq, const float* __restrict__ bk) {
    int bid = blockIdx.x;
    int x = threadIdx.x, y = threadIdx.y;      // 32 x 8
    if (bid == 768) {
        int i = y * 32 + x;
        g_bqk[i] = (i < CD) ? bq[i] : bk[i - CD];
        return;
    }
    const float* src; float* dst; int R, C, tile;
    if (bid < 96)       { src = Wq; dst = g_wqkT;            R = CH; C = CD; tile = bid; }
    else if (bid < 192) { src = Wk; dst = g_wqkT + CD * CH;  R = CH; C = CD; tile = bid - 96; }
    else                { src = Wv; dst = g_wvT;             R = CH; C = CH; tile = bid - 192; }
    int tcols = C >> 5;
    int c0 = (tile % tcols) * 32, r0 = (tile / tcols) * 32;
    __shared__ float t[32][33];
    #pragma unroll
    for (int j = 0; j < 32; j += 8)
        t[y + j][x] = src[(long long)(r0 + y + j) * C + c0 + x];
    __syncthreads();
    #pragma unroll
    for (int j = 0; j < 32; j += 8)
        dst[(long long)(c0 + y + j) * R + r0 + x] = t[x][y + j];
}

// ---------------- feasC1 (+ efea gather): per-bt block ----------------
__global__ void feasC1_kernel(const float* __restrict__ xs, const int* __restrict__ spans,
                              const float* __restrict__ Ww, const float* __restrict__ bw,
                              const float* __restrict__ Wa) {
    int bt = blockIdx.x;           // 32 blocks, 256 threads
    int b = bt >> 1;
    int tid = threadIdx.x;
    int span = spans[bt];
    __shared__ float s_e[CE * CH];     // 24KB
    __shared__ float s_f[CH];
    __shared__ float s_r[4];
    float4* ep = reinterpret_cast<float4*>(&g_efea[bt * CE * CH]);
    #pragma unroll
    for (int j = 0; j < 6; j++) {
        int f = j * 256 + tid;             // over 1536 float4
        int e = f / 192, c4 = f % 192;
        float4 v = *reinterpret_cast<const float4*>(
            &xs[((long long)b * CS + span + e) * CH + c4 * 4]);
        reinterpret_cast<float4*>(s_e)[f] = v;
        ep[f] = v;
    }
    __syncthreads();
    for (int h = tid; h < CH; h += 256) {
        float a = 0.f;
        #pragma unroll
        for (int e = 0; e < CE; e++) a += s_e[e * CH + h];
        s_f[h] = a * (1.0f / CE);
    }
    __syncthreads();
    if (tid < 128) {
        float acc = bw[tid];
        for (int h = 0; h < CH; h++) acc += s_f[h] * Ww[h * CA + tid];
        float part = acc * Wa[tid];
        #pragma unroll
        for (int off = 16; off; off >>= 1) part += __shfl_xor_sync(0xffffffffu, part, off);
        if ((tid & 31) == 0) s_r[tid >> 5] = part;
    }
    __syncthreads();
    if (tid == 0) g_c1[bt] = s_r[0] + s_r[1] + s_r[2] + s_r[3];
}

// ---------------- stage B (vectorized): per-neighbor SDPA + messages + score ----------------
#define KCP (CD + 4)   // 132-word pitch
__global__ void stageB_kernel(const float* __restrict__ neigh, const float* __restrict__ dists,
                              const float* __restrict__ Ww, const float* __restrict__ bw,
                              const float* __restrict__ Wa, const float* __restrict__ ba,
                              const float* __restrict__ wb, const float* __restrict__ bb) {
    int bid = blockIdx.x;                 // B*T*N = 1024 blocks, 256 threads
    int bt = bid / CN, n = bid % CN;
    int tid = threadIdx.x;
    const float inv_sqrt_d = 0.08838834764831845f;

    __shared__ float s_q[CE * CD];        // 4KB; aliased as red4 after logits
    __shared__ float s_kc[CL * KCP];      // 33KB
    __shared__ float s_attn[CE * CL];     // 2KB
    __shared__ float s_pooled[CH];        // 3KB
    __shared__ float s_red[256];          // 1KB

    reinterpret_cast<float4*>(s_q)[tid] =
        reinterpret_cast<const float4*>(&g_qe[bt * CE * CD])[tid];
    {
        const float4* kp = reinterpret_cast<const float4*>(&g_kbuf[(long long)bid * CL * CD]);
        #pragma unroll
        for (int j = 0; j < 8; j++) {
            int f = j * 256 + tid;
            int l = f >> 5, c4 = f & 31;
            *reinterpret_cast<float4*>(&s_kc[l * KCP + c4 * 4]) = kp[f];
        }
    }
    __syncthreads();

    #pragma unroll
    for (int r = 0; r < 2; r++) {
        int o = r * 256 + tid;
        int e = o >> 6, l = o & 63;
        const float4* q4 = reinterpret_cast<const float4*>(&s_q[e * CD]);
        const float4* k4 = reinterpret_cast<const float4*>(&s_kc[l * KCP]);
        float acc = 0.f;
        #pragma unroll 8
        for (int d = 0; d < 32; d++) {
            float4 a = q4[d], b = k4[d];
            acc += a.x * b.x + a.y * b.y + a.z * b.z + a.w * b.w;
        }
        s_attn[o] = acc * inv_sqrt_d;
    }
    __syncthreads();

    {
        int w = tid >> 5, lane = tid & 31;
        if (w < CE) {
            float v1 = s_attn[w * CL + lane], v2 = s_attn[w * CL + lane + 32];
            float m = fmaxf(v1, v2);
            #pragma unroll
            for (int off = 16; off; off >>= 1) m = fmaxf(m, __shfl_xor_sync(0xffffffffu, m, off));
            float e1 = __expf(v1 - m), e2 = __expf(v2 - m);
            float s = e1 + e2;
            #pragma unroll
            for (int off = 16; off; off >>= 1) s += __shfl_xor_sync(0xffffffffu, s, off);
            float inv = 1.0f / s;
            s_attn[w * CL + lane] = e1 * inv;
            s_attn[w * CL + lane + 32] = e2 * inv;
        }
    }
    __syncthreads();

    float* s_red4 = s_q;   // alias
    const long long nb = ((long long)bid) * CL * CH;
    const long long mb = ((long long)bid) * CE * CH;
    int e = tid >> 5, jg = tid & 31;
    for (int hc = 0; hc < CH; hc += 128) {
        #pragma unroll
        for (int j = 0; j < 8; j++) {
            int f = j * 256 + tid;
            int l = f >> 5, c4 = f & 31;
            *reinterpret_cast<float4*>(&s_kc[l * KCP + c4 * 4]) =
                *reinterpret_cast<const float4*>(&neigh[nb + (long long)l * CH + hc + c4 * 4]);
        }
        __syncthreads();
        float4 acc = {0.f, 0.f, 0.f, 0.f};
        const float* at = &s_attn[e * CL];
        #pragma unroll 16
        for (int l = 0; l < CL; l++) {
            float a = at[l];
            float4 k = *reinterpret_cast<const float4*>(&s_kc[l * KCP + jg * 4]);
            acc.x += a * k.x; acc.y += a * k.y; acc.z += a * k.z; acc.w += a * k.w;
        }
        *reinterpret_cast<float4*>(&g_msgs[mb + (long long)e * CH + hc + jg * 4]) = acc;
        *reinterpret_cast<float4*>(&s_red4[tid * 4]) = acc;
        __syncthreads();
        if (tid < 128) {
            int jg2 = tid >> 2, comp = tid & 3;
            float s = 0.f;
            #pragma unroll
            for (int e2 = 0; e2 < CE; e2++) s += s_red4[(e2 * 32 + jg2) * 4 + comp];
            s_pooled[hc + tid] = s * (1.0f / CE);
        }
        __syncthreads();
    }

    float part = 0.f;
    if (tid < CA) {
        float acc = bw[tid];
        for (int h = 0; h < CH; h++) acc += s_pooled[h] * Ww[h * CA + tid];
        part = acc * Wa[CA + tid];
    }
    s_red[tid] = part;
    __syncthreads();
    for (int s = 128; s > 0; s >>= 1) {
        if (tid < s) s_red[tid] += s_red[tid + s];
        __syncthreads();
    }
    if (tid == 0) {
        float v = g_c1[bt] + s_red[0] + ba[0];
        v = (v > 0.f) ? v : 0.01f * v;
        v += dists[bt * CN + n] * wb[0] + bb[0];
        g_score[bt * CN + n] = 1.0f / (1.0f + __expf(-v));
    }
}

// ---------------- fused copy + scatter: x = xs, spans get score-weighted messages ----------------
__global__ void copy_scatter_kernel(const float* __restrict__ xs, const int* __restrict__ spans) {
    int i4 = blockIdx.x * blockDim.x + threadIdx.x;      // over B*S*H/4 = 1572864
    const int total4 = CB * CS * CH / 4;
    if (i4 >= total4) return;
    int f = i4 * 4;
    int b = f / (CS * CH);
    int r = f % (CS * CH);
    int s = r / CH, h = r % CH;
    float4 v = reinterpret_cast<const float4*>(xs)[i4];
    #pragma unroll
    for (int t = 0; t < 2; t++) {
        int bt = b * CT + t;
        int e = s - spans[bt];
        if (e >= 0 && e < CE) {
            const float* sc = &g_score[bt * CN];
            const float* ms = &g_msgs[(((long long)bt * CN) * CE + e) * CH + h];
            float4 d = {0.f, 0.f, 0.f, 0.f};
            #pragma unroll 8
            for (int n = 0; n < CN; n++) {
                float a = sc[n];
                float4 m = *reinterpret_cast<const float4*>(ms + (long long)n * CE * CH);
                d.x += a * m.x; d.y += a * m.y; d.z += a * m.z; d.w += a * m.w;
            }
            v.x += d.x; v.y += d.y; v.z += d.z; v.w += d.w;
        }
    }
    reinterpret_cast<float4*>(g_x)[i4] = v;
}

// ---------------- row softmax for s2 ----------------
__global__ void softmax_kernel() {
    int row = blockIdx.x;
    int tid = threadIdx.x;
    float* p = &g_s2[(long long)row * CS];
    __shared__ float s_red[256];
    float v1 = p[tid], v2 = p[tid + 256];
    float m = fmaxf(v1, v2);
    s_red[tid] = m;
    __syncthreads();
    for (int s = 128; s > 0; s >>= 1) { if (tid < s) s_red[tid] = fmaxf(s_red[tid], s_red[tid + s]); __syncthreads(); }
    m = s_red[0];
    __syncthreads();
    float e1 = __expf(v1 - m), e2 = __expf(v2 - m);
    s_red[tid] = e1 + e2;
    __syncthreads();
    for (int s = 128; s > 0; s >>= 1) { if (tid < s) s_red[tid] += s_red[tid + s]; __syncthreads(); }
    float inv = 1.0f / s_red[0];
    p[tid] = e1 * inv;
    p[tid + 256] = e2 * inv;
}

// ---------------- host ----------------
extern "C" void kernel_launch(void* const* d_in, const int* in_sizes, int n_in,
                              void* d_out, int out_size) {
    const float* xs    = (const float*)d_in[0];
    const float* neigh = (const float*)d_in[1];
    const float* dists = (const float*)d_in[2];
    const int*   spans = (const int*)d_in[3];
    const float* Wq = (const float*)d_in[4];
    const float* bq = (const float*)d_in[5];
    const float* Wk = (const float*)d_in[6];
    const float* bk = (const float*)d_in[7];
    const float* Wv = (const float*)d_in[8];
    const float* bv = (const float*)d_in[9];
    const float* Ww = (const float*)d_in[10];
    const float* bw = (const float*)d_in[11];
    const float* Wa = (const float*)d_in[12];
    const float* ba = (const float*)d_in[13];
    const float* wb = (const float*)d_in[14];
    const float* bb = (const float*)d_in[15];
    float* out = (float*)d_out;

    float *kbuf, *x, *qk2, *v2T, *s2, *wqkT, *wvT, *bqk, *efea, *qe;
    cudaGetSymbolAddress((void**)&kbuf, g_kbuf);
    cudaGetSymbolAddress((void**)&x,    g_x);
    cudaGetSymbolAddress((void**)&qk2,  g_qk2);
    cudaGetSymbolAddress((void**)&v2T,  g_v2T);
    cudaGetSymbolAddress((void**)&s2,   g_s2);
    cudaGetSymbolAddress((void**)&wqkT, g_wqkT);
    cudaGetSymbolAddress((void**)&wvT,  g_wvT);
    cudaGetSymbolAddress((void**)&bqk,  g_bqk);
    cudaGetSymbolAddress((void**)&efea, g_efea);
    cudaGetSymbolAddress((void**)&qe,   g_qe);

    cudaFuncSetAttribute(mm_gemm_kernel, cudaFuncAttributeMaxDynamicSharedMemorySize, GE_SMEM_BYTES);

    const float inv_sqrt_d = 0.08838834764831845f;

    // all weight prep in one launch
    prep_kernel<<<769, dim3(32, 8)>>>(Wq, Wk, Wv, bq, bk);

    // entity features: gather + feas/c1 (writes g_efea), then qe via GEMM
    feasC1_kernel<<<CB * CT, 256>>>(xs, spans, Ww, bw, Wa);
    mm_gemm_kernel<<<dim3(1, 2, 1), 256, GE_SMEM_BYTES>>>(
        efea, wqkT, bq, qe, CB*CT*CE, CD, CH, 1.0f, CH, CH, CD, 1, 0, 0, 0);

    // k projection: [65536,768] @ WkT^T -> [65536,128]
    mm_gemm_kernel<<<dim3(1, 512, 1), 256, GE_SMEM_BYTES>>>(
        neigh, wqkT + CD * CH, bk, kbuf, CB*CT*CN*CL, CD, CH, 1.0f, CH, CH, CD, 1, 0, 0, 0);

    // per-neighbor SDPA + messages + scores
    stageB_kernel<<<CB * CT * CN, 256>>>(neigh, dists, Ww, bw, Wa, ba, wb, bb);

    // x = xs + scattered deltas (fused, overlap-safe)
    copy_scatter_kernel<<<(CB * CS * CH / 4 + 255) / 256, 256>>>(xs, spans);

    // fused q2|k2 projection: [8192,768] @ wqkT^T -> [8192,256]
    mm_gemm_kernel<<<dim3(2, 64, 1), 256, GE_SMEM_BYTES>>>(
        x, wqkT, bqk, qk2, CB * CS, 2 * CD, CH, 1.0f, CH, CH, 2 * CD, 1, 0, 0, 0);

    // v2T = wvT @ x^T per batch: [768,512], row-bias bv
    mm_gemm_kernel<<<dim3(4, 6, CB), 256, GE_SMEM_BYTES>>>(
        wvT, x, bv, v2T, CH, CS, CH, 1.0f, CH, CH, CS, 2,
        0, (long long)CS * CH, (long long)CH * CS);

    // s2 = q2 @ k2^T * inv_sqrt_d (batched; q2/k2 interleaved in qk2)
    mm_gemm_kernel<<<dim3(4, 4, CB), 256, GE_SMEM_BYTES>>>(
        qk2, qk2 + CD, nullptr, s2, CS, CS, CD, inv_sqrt_d, 2 * CD, 2 * CD, CS, 0,
        (long long)CS * 2 * CD, (long long)CS * 2 * CD, (long long)CS * CS);

    softmax_kernel<<<CB * CS, 256>>>();

    // out = softmax(s2) @ v2  (B operand = v2T [768,512], batched)
    mm_gemm_kernel<<<dim3(6, 4, CB), 256, GE_SMEM_BYTES>>>(
        s2, v2T, nullptr, out, CS, CH, CS, 1.0f, CS, CS, CH, 0,
        (long long)CS * CS, (long long)CH * CS, (long long)CS * CH);
}

// round 17
// speedup vs baseline: 1.9682x; 1.2245x over previous
#include <cuda_runtime.h>
#include <math.h>
#include <stdint.h>

// Problem constants
#define CB 16
#define CS 512
#define CH 768
#define CT 2
#define CN 32
#define CL 64
#define CE 8
#define CD 128
#define CA 128

// ---------------- scratch (device globals; no allocation allowed) ----------------
__device__ float g_kbuf[CB*CT*CN*CL*CD];       // neighbor k projections
__device__ float g_msgs[CB*CT*CN*CE*CH];       // per-neighbor messages
__device__ float g_score[CB*CT*CN];
__device__ float g_c1[CB*CT];
__device__ float g_qe[CB*CT*CE*CD];
__device__ float g_efea[CB*CT*CE*CH];          // gathered entity span features [256,768]
__device__ float g_x[CB*CS*CH];
__device__ float g_qk2[CB*CS*2*CD];            // fused q2|k2 [B*S, 256]
__device__ float g_v2T[CB*CH*CS];              // v2 transposed per batch [B][768][512]
__device__ float g_s2[CB*CS*CS];
__device__ float g_wqkT[2*CD*CH];              // [WqT; WkT] [256,768]
__device__ float g_wvT[CH*CH];
__device__ float g_bqk[2*CD];

// ================= tf32 mma.sync GEMM (CTA 128x128, warp 32x64) =====
// Triple-buffered SMEM, prefetch distance 2: sync -> STS(i+1) -> LDG(i+2) -> MMA(i).
// A [M,K] rows lda, B [N,K] rows ldb, C [M,N] rows ldc. M,N mult 128, K mult 32.
// bias_mode: 0 none, 1 per-col, 2 per-row. Batched via blockIdx.z (strides sA,sB,sC).
// __launch_bounds__(256, 2); ks-XOR swizzled fragment SMEM.

#define GE_SMEM_BYTES 98304   // 3 buffers x (A 16KB + B 16KB)

__device__ __forceinline__ void mma_tf32(float c[4], const uint32_t a[4], const uint32_t b[2]) {
    asm volatile(
        "mma.sync.aligned.m16n8k8.row.col.f32.tf32.tf32.f32 "
        "{%0,%1,%2,%3}, {%4,%5,%6,%7}, {%8,%9}, {%0,%1,%2,%3};"
        : "+f"(c[0]), "+f"(c[1]), "+f"(c[2]), "+f"(c[3])
        : "r"(a[0]), "r"(a[1]), "r"(a[2]), "r"(a[3]), "r"(b[0]), "r"(b[1]));
}

__device__ __forceinline__ void tile_ldg(const float* __restrict__ p, int lda, int tid, float4 r[4]) {
    #pragma unroll
    for (int j = 0; j < 4; j++) {
        int f = j * 256 + tid;
        int row = f >> 3, c4 = f & 7;
        float4 v = *reinterpret_cast<const float4*>(p + (long long)row * lda + c4 * 4);
        asm volatile("cvt.rna.tf32.f32 %0, %0;" : "+r"(*(uint32_t*)&v.x));
        asm volatile("cvt.rna.tf32.f32 %0, %0;" : "+r"(*(uint32_t*)&v.y));
        asm volatile("cvt.rna.tf32.f32 %0, %0;" : "+r"(*(uint32_t*)&v.z));
        asm volatile("cvt.rna.tf32.f32 %0, %0;" : "+r"(*(uint32_t*)&v.w));
        r[j] = v;
    }
}

// A fragment store: slot (g*4+t) ^ ks at [ks][mt][slot][jf]
__device__ __forceinline__ void sts_fragA(float* sm, int tid, const float4 r[4]) {
    #pragma unroll
    for (int j = 0; j < 4; j++) {
        int f = j * 256 + tid;
        int row = f >> 3, c4 = f & 7;
        int ks = c4 >> 1;
        int jfrag = ((row >> 3) & 1) + ((c4 & 1) << 1);
        int mt = row >> 4, g = row & 7;
        float* base = sm + (((ks * 8 + mt) * 32) << 2) + jfrag;
        const float* v = reinterpret_cast<const float*>(&r[j]);
        #pragma unroll
        for (int t = 0; t < 4; t++) base[((g * 4 + t) ^ ks) << 2] = v[t];
    }
}

// B fragment store: slot (g*4+t) ^ ks at [ks][nt][slot][jf]
__device__ __forceinline__ void sts_fragB(float* sm, int tid, const float4 r[4]) {
    #pragma unroll
    for (int j = 0; j < 4; j++) {
        int f = j * 256 + tid;
        int row = f >> 3, c4 = f & 7;
        int ks = c4 >> 1;
        int jfrag = c4 & 1;
        int nt = row >> 3, g = row & 7;
        float* base = sm + (((ks * 16 + nt) * 32) << 1) + jfrag;
        const float* v = reinterpret_cast<const float*>(&r[j]);
        #pragma unroll
        for (int t = 0; t < 4; t++) base[((g * 4 + t) ^ ks) << 1] = v[t];
    }
}

__global__ void __launch_bounds__(256, 2)
mm_gemm_kernel(const float* __restrict__ A, const float* __restrict__ B,
               const float* __restrict__ bias, float* __restrict__ C,
               int M, int N, int K, float alpha,
               int lda, int ldb, int ldc, int bias_mode,
               long long sA, long long sB, long long sC)
{
    extern __shared__ float smem[];
    int tid = threadIdx.x;
    int wid = tid >> 5, lane = tid & 31;
    int warpM = wid & 3;
    int warpN = wid >> 2;

    const float* Ab = A + (long long)blockIdx.z * sA + (long long)(blockIdx.y * 128) * lda;
    const float* Bb = B + (long long)blockIdx.z * sB + (long long)(blockIdx.x * 128) * ldb;

    float acc[2][8][4];
    #pragma unroll
    for (int i = 0; i < 2; i++)
        #pragma unroll
        for (int j = 0; j < 8; j++)
            #pragma unroll
            for (int c = 0; c < 4; c++) acc[i][j][c] = 0.f;

    int nch = K >> 5;
    float4 ra[4], rb[4];
    tile_ldg(Ab, lda, tid, ra);
    tile_ldg(Bb, ldb, tid, rb);
    sts_fragA(smem, tid, ra);
    sts_fragB(smem + 4096, tid, rb);
    if (nch > 1) {
        tile_ldg(Ab + 32, lda, tid, ra);
        tile_ldg(Bb + 32, ldb, tid, rb);
    }

    int buf = 0, nbuf = 1;
    for (int i = 0; i < nch; i++) {
        __syncthreads();
        if (i + 1 < nch) {
            sts_fragA(smem + nbuf * 8192, tid, ra);
            sts_fragB(smem + nbuf * 8192 + 4096, tid, rb);
        }
        if (i + 2 < nch) {
            tile_ldg(Ab + (i + 2) * 32, lda, tid, ra);
            tile_ldg(Bb + (i + 2) * 32, ldb, tid, rb);
        }
        const float* bufA = smem + buf * 8192;
        const float* bufB = smem + buf * 8192 + 4096;
        #pragma unroll
        for (int ks = 0; ks < 4; ks++) {
            int sl = lane ^ ks;
            const float* fA = bufA + (ks * 8 + warpM * 2) * 128 + sl * 4;
            const float* fB = bufB + (ks * 16 + warpN * 8) * 64 + sl * 2;
            uint32_t afr[2][4];
            #pragma unroll
            for (int mt = 0; mt < 2; mt++) {
                float4 v = *reinterpret_cast<const float4*>(fA + mt * 128);
                afr[mt][0] = __float_as_uint(v.x); afr[mt][1] = __float_as_uint(v.y);
                afr[mt][2] = __float_as_uint(v.z); afr[mt][3] = __float_as_uint(v.w);
            }
            #pragma unroll
            for (int nt = 0; nt < 8; nt++) {
                float2 v = *reinterpret_cast<const float2*>(fB + nt * 64);
                uint32_t bfr[2] = { __float_as_uint(v.x), __float_as_uint(v.y) };
                mma_tf32(acc[0][nt], afr[0], bfr);
                mma_tf32(acc[1][nt], afr[1], bfr);
            }
        }
        buf = nbuf;
        nbuf = (nbuf + 1 == 3) ? 0 : nbuf + 1;
    }

    int g = lane >> 2, t = lane & 3;
    long long crow0 = (long long)(blockIdx.y * 128 + warpM * 32 + g);
    int col0 = blockIdx.x * 128 + warpN * 64 + t * 2;
    float* Cb = C + (long long)blockIdx.z * sC;
    #pragma unroll
    for (int mt = 0; mt < 2; mt++) {
        long long r0 = crow0 + mt * 16;
        float br0 = 0.f, br1 = 0.f;
        if (bias_mode == 2) { br0 = bias[r0]; br1 = bias[r0 + 8]; }
        #pragma unroll
        for (int nt = 0; nt < 8; nt++) {
            int cc = col0 + nt * 8;
            float bcx = 0.f, bcy = 0.f;
            if (bias_mode == 1) { bcx = bias[cc]; bcy = bias[cc + 1]; }
            float2 v0 = { acc[mt][nt][0] * alpha + bcx + br0, acc[mt][nt][1] * alpha + bcy + br0 };
            float2 v1 = { acc[mt][nt][2] * alpha + bcx + br1, acc[mt][nt][3] * alpha + bcy + br1 };
            *reinterpret_cast<float2*>(Cb + r0 * ldc + cc) = v0;
            *reinterpret_cast<float2*>(Cb + (r0 + 8) * ldc + cc) = v1;
        }
    }
}

// ---------------- prep: all weight transposes + bias pack in ONE launch ----------------
__global__ void prep_kernel(const float* __restrict__ Wq, const float* __restrict__ Wk,
                            const float* __restrict__ Wv,
                            const float* __restrict__ bq, const float* __restrict__ bk) {
    int bid = blockIdx.x;
    int x = threadIdx.x, y = threadIdx.y;      // 32 x 8
    if (bid == 768) {
        int i = y * 32 + x;
        g_bqk[i] = (i < CD) ? bq[i] : bk[i - CD];
        return;
    }
    const float* src; float* dst; int R, C, tile;
    if (bid < 96)       { src = Wq; dst = g_wqkT;            R = CH; C = CD; tile = bid; }
    else if (bid < 192) { src = Wk; dst = g_wqkT + CD * CH;  R = CH; C = CD; tile = bid - 96; }
    else                { src = Wv; dst = g_wvT;             R = CH; C = CH; tile = bid - 192; }
    int tcols = C >> 5;
    int c0 = (tile % tcols) * 32, r0 = (tile / tcols) * 32;
    __shared__ float t[32][33];
    #pragma unroll
    for (int j = 0; j < 32; j += 8)
        t[y + j][x] = src[(long long)(r0 + y + j) * C + c0 + x];
    __syncthreads();
    #pragma unroll
    for (int j = 0; j < 32; j += 8)
        dst[(long long)(c0 + y + j) * R + r0 + x] = t[x][y + j];
}

// ---------------- feasC1 (+ efea gather): per-bt block ----------------
__global__ void feasC1_kernel(const float* __restrict__ xs, const int* __restrict__ spans,
                              const float* __restrict__ Ww, const float* __restrict__ bw,
                              const float* __restrict__ Wa) {
    int bt = blockIdx.x;           // 32 blocks, 256 threads
    int b = bt >> 1;
    int tid = threadIdx.x;
    int span = spans[bt];
    __shared__ float s_e[CE * CH];     // 24KB
    __shared__ float s_f[CH];
    __shared__ float s_r[4];
    float4* ep = reinterpret_cast<float4*>(&g_efea[bt * CE * CH]);
    #pragma unroll
    for (int j = 0; j < 6; j++) {
        int f = j * 256 + tid;             // over 1536 float4
        int e = f / 192, c4 = f % 192;
        float4 v = *reinterpret_cast<const float4*>(
            &xs[((long long)b * CS + span + e) * CH + c4 * 4]);
        reinterpret_cast<float4*>(s_e)[f] = v;
        ep[f] = v;
    }
    __syncthreads();
    for (int h = tid; h < CH; h += 256) {
        float a = 0.f;
        #pragma unroll
        for (int e = 0; e < CE; e++) a += s_e[e * CH + h];
        s_f[h] = a * (1.0f / CE);
    }
    __syncthreads();
    if (tid < 128) {
        float acc = bw[tid];
        for (int h = 0; h < CH; h++) acc += s_f[h] * Ww[h * CA + tid];
        float part = acc * Wa[tid];
        #pragma unroll
        for (int off = 16; off; off >>= 1) part += __shfl_xor_sync(0xffffffffu, part, off);
        if ((tid & 31) == 0) s_r[tid >> 5] = part;
    }
    __syncthreads();
    if (tid == 0) g_c1[bt] = s_r[0] + s_r[1] + s_r[2] + s_r[3];
}

// ---------------- stage B (vectorized): per-neighbor SDPA + messages + score ----------------
#define KCP (CD + 4)   // 132-word pitch
__global__ void stageB_kernel(const float* __restrict__ neigh, const float* __restrict__ dists,
                              const float* __restrict__ Ww, const float* __restrict__ bw,
                              const float* __restrict__ Wa, const float* __restrict__ ba,
                              const float* __restrict__ wb, const float* __restrict__ bb) {
    int bid = blockIdx.x;                 // B*T*N = 1024 blocks, 256 threads
    int bt = bid / CN, n = bid % CN;
    int tid = threadIdx.x;
    const float inv_sqrt_d = 0.08838834764831845f;

    __shared__ float s_q[CE * CD];        // 4KB; aliased as red4 after logits
    __shared__ float s_kc[CL * KCP];      // 33KB
    __shared__ float s_attn[CE * CL];     // 2KB
    __shared__ float s_pooled[CH];        // 3KB
    __shared__ float s_red[256];          // 1KB

    reinterpret_cast<float4*>(s_q)[tid] =
        reinterpret_cast<const float4*>(&g_qe[bt * CE * CD])[tid];
    {
        const float4* kp = reinterpret_cast<const float4*>(&g_kbuf[(long long)bid * CL * CD]);
        #pragma unroll
        for (int j = 0; j < 8; j++) {
            int f = j * 256 + tid;
            int l = f >> 5, c4 = f & 31;
            *reinterpret_cast<float4*>(&s_kc[l * KCP + c4 * 4]) = kp[f];
        }
    }
    __syncthreads();

    #pragma unroll
    for (int r = 0; r < 2; r++) {
        int o = r * 256 + tid;
        int e = o >> 6, l = o & 63;
        const float4* q4 = reinterpret_cast<const float4*>(&s_q[e * CD]);
        const float4* k4 = reinterpret_cast<const float4*>(&s_kc[l * KCP]);
        float acc = 0.f;
        #pragma unroll 8
        for (int d = 0; d < 32; d++) {
            float4 a = q4[d], b = k4[d];
            acc += a.x * b.x + a.y * b.y + a.z * b.z + a.w * b.w;
        }
        s_attn[o] = acc * inv_sqrt_d;
    }
    __syncthreads();

    {
        int w = tid >> 5, lane = tid & 31;
        if (w < CE) {
            float v1 = s_attn[w * CL + lane], v2 = s_attn[w * CL + lane + 32];
            float m = fmaxf(v1, v2);
            #pragma unroll
            for (int off = 16; off; off >>= 1) m = fmaxf(m, __shfl_xor_sync(0xffffffffu, m, off));
            float e1 = __expf(v1 - m), e2 = __expf(v2 - m);
            float s = e1 + e2;
            #pragma unroll
            for (int off = 16; off; off >>= 1) s += __shfl_xor_sync(0xffffffffu, s, off);
            float inv = 1.0f / s;
            s_attn[w * CL + lane] = e1 * inv;
            s_attn[w * CL + lane + 32] = e2 * inv;
        }
    }
    __syncthreads();

    float* s_red4 = s_q;   // alias
    const long long nb = ((long long)bid) * CL * CH;
    const long long mb = ((long long)bid) * CE * CH;
    int e = tid >> 5, jg = tid & 31;
    for (int hc = 0; hc < CH; hc += 128) {
        #pragma unroll
        for (int j = 0; j < 8; j++) {
            int f = j * 256 + tid;
            int l = f >> 5, c4 = f & 31;
            *reinterpret_cast<float4*>(&s_kc[l * KCP + c4 * 4]) =
                *reinterpret_cast<const float4*>(&neigh[nb + (long long)l * CH + hc + c4 * 4]);
        }
        __syncthreads();
        float4 acc = {0.f, 0.f, 0.f, 0.f};
        const float* at = &s_attn[e * CL];
        #pragma unroll 16
        for (int l = 0; l < CL; l++) {
            float a = at[l];
            float4 k = *reinterpret_cast<const float4*>(&s_kc[l * KCP + jg * 4]);
            acc.x += a * k.x; acc.y += a * k.y; acc.z += a * k.z; acc.w += a * k.w;
        }
        *reinterpret_cast<float4*>(&g_msgs[mb + (long long)e * CH + hc + jg * 4]) = acc;
        *reinterpret_cast<float4*>(&s_red4[tid * 4]) = acc;
        __syncthreads();
        if (tid < 128) {
            int jg2 = tid >> 2, comp = tid & 3;
            float s = 0.f;
            #pragma unroll
            for (int e2 = 0; e2 < CE; e2++) s += s_red4[(e2 * 32 + jg2) * 4 + comp];
            s_pooled[hc + tid] = s * (1.0f / CE);
        }
        __syncthreads();
    }

    float part = 0.f;
    if (tid < CA) {
        float acc = bw[tid];
        for (int h = 0; h < CH; h++) acc += s_pooled[h] * Ww[h * CA + tid];
        part = acc * Wa[CA + tid];
    }
    s_red[tid] = part;
    __syncthreads();
    for (int s = 128; s > 0; s >>= 1) {
        if (tid < s) s_red[tid] += s_red[tid + s];
        __syncthreads();
    }
    if (tid == 0) {
        float v = g_c1[bt] + s_red[0] + ba[0];
        v = (v > 0.f) ? v : 0.01f * v;
        v += dists[bt * CN + n] * wb[0] + bb[0];
        g_score[bt * CN + n] = 1.0f / (1.0f + __expf(-v));
    }
}

// ---------------- fused copy + scatter: x = xs, spans get score-weighted messages ----------------
__global__ void copy_scatter_kernel(const float* __restrict__ xs, const int* __restrict__ spans) {
    int i4 = blockIdx.x * blockDim.x + threadIdx.x;      // over B*S*H/4 = 1572864
    const int total4 = CB * CS * CH / 4;
    if (i4 >= total4) return;
    int f = i4 * 4;
    int b = f / (CS * CH);
    int r = f % (CS * CH);
    int s = r / CH, h = r % CH;
    float4 v = reinterpret_cast<const float4*>(xs)[i4];
    #pragma unroll
    for (int t = 0; t < 2; t++) {
        int bt = b * CT + t;
        int e = s - spans[bt];
        if (e >= 0 && e < CE) {
            const float* sc = &g_score[bt * CN];
            const float* ms = &g_msgs[(((long long)bt * CN) * CE + e) * CH + h];
            float4 d = {0.f, 0.f, 0.f, 0.f};
            #pragma unroll 8
            for (int n = 0; n < CN; n++) {
                float a = sc[n];
                float4 m = *reinterpret_cast<const float4*>(ms + (long long)n * CE * CH);
                d.x += a * m.x; d.y += a * m.y; d.z += a * m.z; d.w += a * m.w;
            }
            v.x += d.x; v.y += d.y; v.z += d.z; v.w += d.w;
        }
    }
    reinterpret_cast<float4*>(g_x)[i4] = v;
}

// ---------------- warp-per-row softmax for s2 (no block syncs) ----------------
__global__ void softmax_kernel() {
    int row = blockIdx.x * 8 + (threadIdx.x >> 5);      // 1024 blocks x 8 warps
    int lane = threadIdx.x & 31;
    float4* p = reinterpret_cast<float4*>(&g_s2[(long long)row * CS]);
    float4 v[4];
    float m = -1e30f;
    #pragma unroll
    for (int j = 0; j < 4; j++) {
        v[j] = p[j * 32 + lane];
        m = fmaxf(m, fmaxf(fmaxf(v[j].x, v[j].y), fmaxf(v[j].z, v[j].w)));
    }
    #pragma unroll
    for (int off = 16; off; off >>= 1) m = fmaxf(m, __shfl_xor_sync(0xffffffffu, m, off));
    float s = 0.f;
    #pragma unroll
    for (int j = 0; j < 4; j++) {
        v[j].x = __expf(v[j].x - m); v[j].y = __expf(v[j].y - m);
        v[j].z = __expf(v[j].z - m); v[j].w = __expf(v[j].w - m);
        s += v[j].x + v[j].y + v[j].z + v[j].w;
    }
    #pragma unroll
    for (int off = 16; off; off >>= 1) s += __shfl_xor_sync(0xffffffffu, s, off);
    float inv = 1.0f / s;
    #pragma unroll
    for (int j = 0; j < 4; j++) {
        v[j].x *= inv; v[j].y *= inv; v[j].z *= inv; v[j].w *= inv;
        p[j * 32 + lane] = v[j];
    }
}

// ---------------- host ----------------
extern "C" void kernel_launch(void* const* d_in, const int* in_sizes, int n_in,
                              void* d_out, int out_size) {
    const float* xs    = (const float*)d_in[0];
    const float* neigh = (const float*)d_in[1];
    const float* dists = (const float*)d_in[2];
    const int*   spans = (const int*)d_in[3];
    const float* Wq = (const float*)d_in[4];
    const float* bq = (const float*)d_in[5];
    const float* Wk = (const float*)d_in[6];
    const float* bk = (const float*)d_in[7];
    const float* Wv = (const float*)d_in[8];
    const float* bv = (const float*)d_in[9];
    const float* Ww = (const float*)d_in[10];
    const float* bw = (const float*)d_in[11];
    const float* Wa = (const float*)d_in[12];
    const float* ba = (const float*)d_in[13];
    const float* wb = (const float*)d_in[14];
    const float* bb = (const float*)d_in[15];
    float* out = (float*)d_out;

    float *kbuf, *x, *qk2, *v2T, *s2, *wqkT, *wvT, *bqk, *efea, *qe;
    cudaGetSymbolAddress((void**)&kbuf, g_kbuf);
    cudaGetSymbolAddress((void**)&x,    g_x);
    cudaGetSymbolAddress((void**)&qk2,  g_qk2);
    cudaGetSymbolAddress((void**)&v2T,  g_v2T);
    cudaGetSymbolAddress((void**)&s2,   g_s2);
    cudaGetSymbolAddress((void**)&wqkT, g_wqkT);
    cudaGetSymbolAddress((void**)&wvT,  g_wvT);
    cudaGetSymbolAddress((void**)&bqk,  g_bqk);
    cudaGetSymbolAddress((void**)&efea, g_efea);
    cudaGetSymbolAddress((void**)&qe,   g_qe);

    cudaFuncSetAttribute(mm_gemm_kernel, cudaFuncAttributeMaxDynamicSharedMemorySize, GE_SMEM_BYTES);

    const float inv_sqrt_d = 0.08838834764831845f;

    // side stream + events (created once; capture-safe, no device allocation)
    static cudaStream_t s1 = nullptr;
    static cudaEvent_t evRoot = nullptr, evPrep = nullptr, evQe = nullptr, evX = nullptr, evV = nullptr;
    if (!s1) {
        cudaStreamCreateWithFlags(&s1, cudaStreamNonBlocking);
        cudaEventCreateWithFlags(&evRoot, cudaEventDisableTiming);
        cudaEventCreateWithFlags(&evPrep, cudaEventDisableTiming);
        cudaEventCreateWithFlags(&evQe,   cudaEventDisableTiming);
        cudaEventCreateWithFlags(&evX,    cudaEventDisableTiming);
        cudaEventCreateWithFlags(&evV,    cudaEventDisableTiming);
    }

    // fork side stream from origin
    cudaEventRecord(evRoot, 0);
    cudaStreamWaitEvent(s1, evRoot, 0);

    // s1: feasC1 (independent of prep)
    feasC1_kernel<<<CB * CT, 256, 0, s1>>>(xs, spans, Ww, bw, Wa);

    // main: prep, then record for s1's qe
    prep_kernel<<<769, dim3(32, 8)>>>(Wq, Wk, Wv, bq, bk);
    cudaEventRecord(evPrep, 0);

    // main: k projection (512 blocks) — runs concurrent with s1's qe
    mm_gemm_kernel<<<dim3(1, 512, 1), 256, GE_SMEM_BYTES>>>(
        neigh, wqkT + CD * CH, bk, kbuf, CB*CT*CN*CL, CD, CH, 1.0f, CH, CH, CD, 1, 0, 0, 0);

    // s1: qe GEMM (needs prep + feasC1)
    cudaStreamWaitEvent(s1, evPrep, 0);
    mm_gemm_kernel<<<dim3(1, 2, 1), 256, GE_SMEM_BYTES, s1>>>(
        efea, wqkT, bq, qe, CB*CT*CE, CD, CH, 1.0f, CH, CH, CD, 1, 0, 0, 0);
    cudaEventRecord(evQe, s1);

    // main: stageB (needs kbuf + qe + c1)
    cudaStreamWaitEvent(0, evQe, 0);
    stageB_kernel<<<CB * CT * CN, 256>>>(neigh, dists, Ww, bw, Wa, ba, wb, bb);

    // main: x = xs + scattered deltas
    copy_scatter_kernel<<<(CB * CS * CH / 4 + 255) / 256, 256>>>(xs, spans);
    cudaEventRecord(evX, 0);

    // s1: v2T = wvT @ x^T per batch (needs x + wvT)  — overlaps q2k2/s2/softmax
    cudaStreamWaitEvent(s1, evX, 0);
    mm_gemm_kernel<<<dim3(4, 6, CB), 256, GE_SMEM_BYTES, s1>>>(
        wvT, x, bv, v2T, CH, CS, CH, 1.0f, CH, CH, CS, 2,
        0, (long long)CS * CH, (long long)CH * CS);
    cudaEventRecord(evV, s1);

    // main: fused q2|k2 projection
    mm_gemm_kernel<<<dim3(2, 64, 1), 256, GE_SMEM_BYTES>>>(
        x, wqkT, bqk, qk2, CB * CS, 2 * CD, CH, 1.0f, CH, CH, 2 * CD, 1, 0, 0, 0);

    // main: s2 = q2 @ k2^T * inv_sqrt_d
    mm_gemm_kernel<<<dim3(4, 4, CB), 256, GE_SMEM_BYTES>>>(
        qk2, qk2 + CD, nullptr, s2, CS, CS, CD, inv_sqrt_d, 2 * CD, 2 * CD, CS, 0,
        (long long)CS * 2 * CD, (long long)CS * 2 * CD, (long long)CS * CS);

    // main: softmax (warp-per-row)
    softmax_kernel<<<CB * CS / 8, 256>>>();

    // main: out = softmax(s2) @ v2 (join with v2T)
    cudaStreamWaitEvent(0, evV, 0);
    mm_gemm_kernel<<<dim3(6, 4, CB), 256, GE_SMEM_BYTES>>>(
        s2, v2T, nullptr, out, CS, CH, CS, 1.0f, CS, CS, CH, 0,
        (long long)CS * CS, (long long)CH * CS, (long long)CS * CH);
}